// round 12
// baseline (speedup 1.0000x reference)
#include <cuda_runtime.h>
#include <cuda_bf16.h>
#include <math.h>

#define NSAMP 8
#define NTOK  32768

typedef unsigned long long ull;

// ---------------- helpers ----------------
__device__ __forceinline__ void fma2(ull& d, ull a, ull b) {
    asm("fma.rn.f32x2 %0, %1, %2, %0;" : "+l"(d) : "l"(a), "l"(b));
}
__device__ __forceinline__ ull b2p(unsigned u) {
    unsigned lo = u << 16, hi = u & 0xffff0000u;
    ull r; asm("mov.b64 %0, {%1,%2};" : "=l"(r) : "r"(lo), "r"(hi));
    return r;
}
__device__ __forceinline__ ull dup2(float e) {
    ull r; asm("mov.b64 %0, {%1,%1};" : "=l"(r) : "f"(e));
    return r;
}
__device__ __forceinline__ float2 up2(ull v) {
    float2 f;
    asm("mov.b64 {%0,%1}, %2;" : "=f"(f.x), "=f"(f.y) : "l"(v));
    return f;
}
__device__ __forceinline__ __nv_bfloat162 asbf2(unsigned u) {
    return *reinterpret_cast<__nv_bfloat162*>(&u);
}

// ---------------- mma.sync m16n8k16 bf16 ----------------
__device__ __forceinline__ void mma16816(float* d, unsigned a0, unsigned a1,
                                         unsigned a2, unsigned a3,
                                         unsigned b0, unsigned b1) {
    asm("mma.sync.aligned.m16n8k16.row.col.f32.bf16.bf16.f32 "
        "{%0,%1,%2,%3}, {%4,%5,%6,%7}, {%8,%9}, {%0,%1,%2,%3};"
        : "+f"(d[0]), "+f"(d[1]), "+f"(d[2]), "+f"(d[3])
        : "r"(a0), "r"(a1), "r"(a2), "r"(a3), "r"(b0), "r"(b1));
}

// ---------------- scratch ----------------
__device__ float g_part[256][2];
__device__ __nv_bfloat16 g_qb[NTOK * 64];
__device__ __nv_bfloat16 g_kb[NTOK * 64];
__device__ __nv_bfloat16 g_vb[NTOK * 64];
__device__ __nv_bfloat16 g_ab[NTOK * 64];
__device__ float g_y[NTOK * 64];

// ---------------- K1: per-sample partial sum / sumsq ----------------
__global__ void k_stats1(const float* __restrict__ x) {
    __shared__ float rs_[256], rq_[256];
    int b = blockIdx.x;
    int n = b >> 5, ch = b & 31;
    const float4* p = (const float4*)(x + (size_t)n * 262144 + (size_t)ch * 8192);
    float s = 0.f, sq = 0.f;
#pragma unroll
    for (int i = 0; i < 8; i++) {
        float4 v = p[threadIdx.x + i * 256];
        s  += v.x + v.y + v.z + v.w;
        sq += v.x * v.x + v.y * v.y + v.z * v.z + v.w * v.w;
    }
    rs_[threadIdx.x] = s; rq_[threadIdx.x] = sq;
    __syncthreads();
    for (int st = 128; st > 0; st >>= 1) {
        if (threadIdx.x < st) {
            rs_[threadIdx.x] += rs_[threadIdx.x + st];
            rq_[threadIdx.x] += rq_[threadIdx.x + st];
        }
        __syncthreads();
    }
    if (threadIdx.x == 0) { g_part[b][0] = rs_[0]; g_part[b][1] = rq_[0]; }
}

// ---------------- K3: stats-finalize + norm + QKV (64->192) via bf16 mma ----------------
// 512 blocks x 128 thr; 64 tokens/block; ~38KB smem -> 5-6 co-resident blocks
__global__ __launch_bounds__(128) void k_qkv(const float* __restrict__ x,
                      const float* __restrict__ gw, const float* __restrict__ gb,
                      const float* __restrict__ qkvw, const float* __restrict__ qkvb) {
    extern __shared__ __align__(16) char smraw[];
    __nv_bfloat16* sxa = (__nv_bfloat16*)smraw;           // 64*76  (9728B)
    __nv_bfloat16* sw  = (__nv_bfloat16*)(smraw + 9728);  // 192*72 (27648B)
    float* sb = (float*)(smraw + 37376);                  // 192
    __shared__ float s_mu, s_rs;
    int tid = threadIdx.x;
    int t0 = blockIdx.x * 64;
    int n = t0 >> 12, ij0 = t0 & 4095;
    for (int i = tid; i < 6144; i += 128) {               // qkvw as float2 -> bf16x2
        float2 wv = ((const float2*)qkvw)[i];
        int r = i >> 5, c2 = (i & 31) * 2;
        *(__nv_bfloat162*)(sw + r * 72 + c2) = __floats2bfloat162_rn(wv.x, wv.y);
    }
    for (int i = tid; i < 192; i += 128) sb[i] = qkvb[i];
    if (tid < 32) {   // per-sample stats finalize
        float s  = g_part[n * 32 + tid][0];
        float sq = g_part[n * 32 + tid][1];
#pragma unroll
        for (int st = 16; st > 0; st >>= 1) {
            s  += __shfl_xor_sync(0xffffffffu, s, st);
            sq += __shfl_xor_sync(0xffffffffu, sq, st);
        }
        if (tid == 0) {
            float mu  = s * (1.f / 262144.f);
            float var = sq * (1.f / 262144.f) - mu * mu;
            s_mu = mu;
            s_rs = rsqrtf(var + 1e-5f);
        }
    }
    __syncthreads();
    float mu = s_mu, rs = s_rs;
    {
        int tl = tid & 63, cb = tid >> 6;
#pragma unroll
        for (int p = 0; p < 32; p++) {
            int c = cb + (p << 1);
            float xv = x[(size_t)n * 262144 + (size_t)c * 4096 + ij0 + tl];
            sxa[tl * 76 + c] = __float2bfloat16((xv - mu) * rs * gw[c] + gb[c]);
        }
    }
    __syncthreads();
    int lane = tid & 31, wrp = tid >> 5;                  // 4 warps, m16 each
    int g = lane >> 2, tt = lane & 3;
    int r0 = wrp * 16 + g, r1 = r0 + 8;
    unsigned a0[4], a1[4], a2[4], a3[4];
#pragma unroll
    for (int kk = 0; kk < 4; kk++) {
        int kbv = kk * 16;
        a0[kk] = *(const unsigned*)(sxa + r0 * 76 + kbv + tt * 2);
        a1[kk] = *(const unsigned*)(sxa + r1 * 76 + kbv + tt * 2);
        a2[kk] = *(const unsigned*)(sxa + r0 * 76 + kbv + 8 + tt * 2);
        a3[kk] = *(const unsigned*)(sxa + r1 * 76 + kbv + 8 + tt * 2);
    }
    size_t tok0 = (size_t)(t0 + r0) * 64, tok1 = (size_t)(t0 + r1) * 64;
#pragma unroll
    for (int jj = 0; jj < 24; jj++) {
        int nn = jj * 8 + g;
        float acc[4] = {0.f, 0.f, 0.f, 0.f};
#pragma unroll
        for (int kk = 0; kk < 4; kk++) {
            unsigned b0 = *(const unsigned*)(sw + nn * 72 + kk * 16 + tt * 2);
            unsigned b1 = *(const unsigned*)(sw + nn * 72 + kk * 16 + 8 + tt * 2);
            mma16816(acc, a0[kk], a1[kk], a2[kk], a3[kk], b0, b1);
        }
        int f0 = jj * 8 + tt * 2;
        float e00 = acc[0] + sb[f0], e01 = acc[1] + sb[f0 + 1];
        float e10 = acc[2] + sb[f0], e11 = acc[3] + sb[f0 + 1];
        if (f0 < 64) {
            *(__nv_bfloat162*)(g_qb + tok0 + f0) = __floats2bfloat162_rn(e00 * 0.25f, e01 * 0.25f);
            *(__nv_bfloat162*)(g_qb + tok1 + f0) = __floats2bfloat162_rn(e10 * 0.25f, e11 * 0.25f);
        } else if (f0 < 128) {
            *(__nv_bfloat162*)(g_kb + tok0 + f0 - 64) = __floats2bfloat162_rn(e00, e01);
            *(__nv_bfloat162*)(g_kb + tok1 + f0 - 64) = __floats2bfloat162_rn(e10, e11);
        } else {
            *(__nv_bfloat162*)(g_vb + tok0 + f0 - 128) = __floats2bfloat162_rn(e00, e01);
            *(__nv_bfloat162*)(g_vb + tok1 + f0 - 128) = __floats2bfloat162_rn(e10, e11);
        }
    }
}

// ---------------- K4: 7x7 neighborhood attention ----------------
#define WMX 14
#define PB  72
__global__ __launch_bounds__(256, 4) void k_attn(const float* __restrict__ rpb) {
    extern __shared__ __align__(16) char smraw[];
    __nv_bfloat16* skb = (__nv_bfloat16*)smraw;        // 196*72
    __nv_bfloat16* svb = skb + 196 * PB;               // 196*72
    int tid = threadIdx.x, b = blockIdx.x;
    int n = b >> 6, t = b & 63;
    int i0 = (t >> 3) << 3, j0 = (t & 7) << 3;
    int rlo = max(i0 - 3, 0), rhi = min(i0 + 10, 63);
    int clo = max(j0 - 3, 0), chi = min(j0 + 10, 63);
    int nr = rhi - rlo + 1, nc = chi - clo + 1;
    int tot = nr * nc * 8;
    for (int idx = tid; idx < tot; idx += 256) {
        int c8 = idx & 7, p = idx >> 3;
        int lr = p / nc, lc = p - lr * nc;
        size_t gt = ((size_t)(n << 12) + ((rlo + lr) << 6) + (clo + lc)) * 64;
        uint4 kv = ((const uint4*)(g_kb + gt))[c8];
        uint4 vv = ((const uint4*)(g_vb + gt))[c8];
        int pp = lr * WMX + lc;
        ((uint4*)(skb + pp * PB))[c8] = kv;
        ((uint4*)(svb + pp * PB))[c8] = vv;
    }
    __syncthreads();

    int h = tid >> 6, q = tid & 63;
    int qi = q >> 3, qj = q & 7;
    int i = i0 + qi, j = j0 + qj;
    int sh_ = min(max(i - 3, 0), 57), sw_ = min(max(j - 3, 0), 57);
    int lsh = sh_ - rlo, lsw = sw_ - clo;
    int bh = i - sh_ + 6, bw = j - sw_ + 6;
    size_t tok = (size_t)(n << 12) + (i << 6) + j;
    const uint4* qp = (const uint4*)(g_qb + tok * 64 + h * 16);
    uint4 Q0 = qp[0], Q1 = qp[1];
    __nv_bfloat162 qh[8];
    qh[0] = asbf2(Q0.x); qh[1] = asbf2(Q0.y); qh[2] = asbf2(Q0.z); qh[3] = asbf2(Q0.w);
    qh[4] = asbf2(Q1.x); qh[5] = asbf2(Q1.y); qh[6] = asbf2(Q1.z); qh[7] = asbf2(Q1.w);
    const __nv_bfloat16* kb = skb + (lsh * WMX + lsw) * PB + h * 16;
    const __nv_bfloat16* vb = svb + (lsh * WMX + lsw) * PB + h * 16;
    const float* rbg = rpb + h * 169 + bh * 13 + bw;
    const __nv_bfloat162 hz = __floats2bfloat162_rn(0.f, 0.f);
    ull vacc[8] = {};
    float ssum = 0.f;
    for (int ah = 0; ah < 7; ah++) {
#pragma unroll
        for (int aw = 0; aw < 7; aw++) {
            int po = (ah * WMX + aw) * PB;
            const uint4* kp = (const uint4*)(kb + po);
            uint4 A = kp[0], B = kp[1];
            __nv_bfloat162 ac0 = hz, ac1 = hz;
            ac0 = __hfma2(qh[0], asbf2(A.x), ac0);
            ac1 = __hfma2(qh[1], asbf2(A.y), ac1);
            ac0 = __hfma2(qh[2], asbf2(A.z), ac0);
            ac1 = __hfma2(qh[3], asbf2(A.w), ac1);
            ac0 = __hfma2(qh[4], asbf2(B.x), ac0);
            ac1 = __hfma2(qh[5], asbf2(B.y), ac1);
            ac0 = __hfma2(qh[6], asbf2(B.z), ac0);
            ac1 = __hfma2(qh[7], asbf2(B.w), ac1);
            __nv_bfloat162 hs = __hadd2(ac0, ac1);
            float s = __bfloat162float(__low2bfloat16(hs))
                    + __bfloat162float(__high2bfloat16(hs))
                    + __ldg(rbg - (ah * 13 + aw));
            float e = __expf(s);
            ssum += e;
            ull e2 = dup2(e);
            const uint4* vp = (const uint4*)(vb + po);
            uint4 VA = vp[0], VB = vp[1];
            fma2(vacc[0], e2, b2p(VA.x));
            fma2(vacc[1], e2, b2p(VA.y));
            fma2(vacc[2], e2, b2p(VA.z));
            fma2(vacc[3], e2, b2p(VA.w));
            fma2(vacc[4], e2, b2p(VB.x));
            fma2(vacc[5], e2, b2p(VB.y));
            fma2(vacc[6], e2, b2p(VB.z));
            fma2(vacc[7], e2, b2p(VB.w));
        }
    }
    float inv = __fdividef(1.f, ssum);
    __nv_bfloat162* op = (__nv_bfloat162*)(g_ab + tok * 64 + h * 16);
#pragma unroll
    for (int d = 0; d < 8; d++) {
        float2 f = up2(vacc[d]);
        op[d] = __floats2bfloat162_rn(f.x * inv, f.y * inv);
    }
}

// ---------------- K5: out-proj (64->64) + residual via bf16 mma ----------------
// 512 blocks x 128 thr; 64 tokens/block; ~35.5KB smem -> 6 co-resident blocks
__global__ __launch_bounds__(128) void k_proj(const float* __restrict__ x,
                       const float* __restrict__ pw, const float* __restrict__ pb) {
    extern __shared__ __align__(16) char smraw[];
    __nv_bfloat16* sa = (__nv_bfloat16*)smraw;            // 64*72 (9216B)
    __nv_bfloat16* sw = (__nv_bfloat16*)(smraw + 9216);   // 64*72 (9216B)
    float* sxr = (float*)(smraw + 18432);                 // 64*66 (16896B)
    float* sbp = (float*)(smraw + 35328);                 // 64
    int tid = threadIdx.x;
    int t0 = blockIdx.x * 64;
    int n = t0 >> 12, ij0 = t0 & 4095;
    for (int i = tid; i < 2048; i += 128) {               // pw as float2 -> bf16x2
        float2 wv = ((const float2*)pw)[i];
        int r = i >> 5, c2 = (i & 31) * 2;
        *(__nv_bfloat162*)(sw + r * 72 + c2) = __floats2bfloat162_rn(wv.x, wv.y);
    }
    if (tid < 64) sbp[tid] = pb[tid];
    for (int idx = tid; idx < 512; idx += 128) {
        int tk = idx >> 3, c8 = idx & 7;
        *(uint4*)(sa + tk * 72 + c8 * 8) =
            ((const uint4*)(g_ab + (size_t)(t0 + tk) * 64))[c8];
    }
    {
        int tl = tid & 63, cb = tid >> 6;
#pragma unroll
        for (int p = 0; p < 32; p++) {
            int c = cb + (p << 1);
            sxr[tl * 66 + c] = x[(size_t)n * 262144 + (size_t)c * 4096 + ij0 + tl];
        }
    }
    __syncthreads();
    int lane = tid & 31, wrp = tid >> 5;                  // 4 warps, m16 each
    int g = lane >> 2, tt = lane & 3;
    int r0 = wrp * 16 + g, r1 = r0 + 8;
    unsigned a0[4], a1[4], a2[4], a3[4];
#pragma unroll
    for (int kk = 0; kk < 4; kk++) {
        int kbv = kk * 16;
        a0[kk] = *(const unsigned*)(sa + r0 * 72 + kbv + tt * 2);
        a1[kk] = *(const unsigned*)(sa + r1 * 72 + kbv + tt * 2);
        a2[kk] = *(const unsigned*)(sa + r0 * 72 + kbv + 8 + tt * 2);
        a3[kk] = *(const unsigned*)(sa + r1 * 72 + kbv + 8 + tt * 2);
    }
    size_t tok0 = (size_t)(t0 + r0) * 64, tok1 = (size_t)(t0 + r1) * 64;
#pragma unroll
    for (int jj = 0; jj < 8; jj++) {
        int nn = jj * 8 + g;
        float acc[4] = {0.f, 0.f, 0.f, 0.f};
#pragma unroll
        for (int kk = 0; kk < 4; kk++) {
            unsigned b0 = *(const unsigned*)(sw + nn * 72 + kk * 16 + tt * 2);
            unsigned b1 = *(const unsigned*)(sw + nn * 72 + kk * 16 + 8 + tt * 2);
            mma16816(acc, a0[kk], a1[kk], a2[kk], a3[kk], b0, b1);
        }
        int c0 = jj * 8 + tt * 2;
        *(float2*)(g_y + tok0 + c0) = make_float2(
            acc[0] + sbp[c0] + sxr[r0 * 66 + c0],
            acc[1] + sbp[c0 + 1] + sxr[r0 * 66 + c0 + 1]);
        *(float2*)(g_y + tok1 + c0) = make_float2(
            acc[2] + sbp[c0] + sxr[r1 * 66 + c0],
            acc[3] + sbp[c0 + 1] + sxr[r1 * 66 + c0 + 1]);
    }
}

// ---------------- K6: LN + fc1 + GELU + fc2 + residual + NCHW ----------------
__global__ __launch_bounds__(512, 2) void k_mlp(const float* __restrict__ lw, const float* __restrict__ lb,
                      const float* __restrict__ w1, const float* __restrict__ b1,
                      const float* __restrict__ w2, const float* __restrict__ b2,
                      float* __restrict__ out) {
    extern __shared__ __align__(16) char smraw[];
    float* syn = (float*)smraw;                           // 32*66 f32  (8448B)
    __nv_bfloat16* sxa = (__nv_bfloat16*)(smraw + 8448);  // 32*72     (4608B)
    __nv_bfloat16* w1s = (__nv_bfloat16*)(smraw + 13056); // 256*72    (36864B)
    __nv_bfloat16* w2s = (__nv_bfloat16*)(smraw + 49920); // 64*264    (33792B)
    __nv_bfloat16* sh  = (__nv_bfloat16*)(smraw + 83712); // 32*264    (16896B)
    float* sb1 = (float*)(smraw + 100608);                // 256
    float* sb2 = (float*)(smraw + 101632);                // 64
    int tid = threadIdx.x;
    for (int i = tid; i < 16384; i += 512)
        w1s[(i >> 6) * 72 + (i & 63)] = __float2bfloat16(w1[i]);
    for (int i = tid; i < 16384; i += 512)
        w2s[(i >> 8) * 264 + (i & 255)] = __float2bfloat16(w2[i]);
    if (tid < 256) sb1[tid] = b1[tid];
    if (tid < 64)  sb2[tid] = b2[tid];
    __syncthreads();

    int lane = tid & 31, wrp = tid >> 5;           // 16 warps
    int g = lane >> 2, tt = lane & 3;
    int mi = wrp & 1, ngrp = wrp >> 1;             // 2 m-tiles x 8 n-groups
    int r0 = mi * 16 + g, r1 = r0 + 8;

    for (int it = 0; it < 4; it++) {
        int t0 = blockIdx.x * 128 + it * 32;
        int n = t0 >> 12, ij0 = t0 & 4095;
        for (int i = tid; i < 2048; i += 512)
            syn[(i >> 6) * 66 + (i & 63)] = g_y[(size_t)t0 * 64 + i];
        __syncthreads();
        {   // LayerNorm -> sxa bf16 (16 threads/token, 4 ch each)
            int tl = tid >> 4, qq = tid & 15;
            float s = 0.f, sq = 0.f;
#pragma unroll
            for (int cc = 0; cc < 4; cc++) {
                float v = syn[tl * 66 + qq * 4 + cc];
                s += v; sq += v * v;
            }
#pragma unroll
            for (int st = 1; st < 16; st <<= 1) {
                s  += __shfl_xor_sync(0xffffffffu, s, st);
                sq += __shfl_xor_sync(0xffffffffu, sq, st);
            }
            float mu = s * (1.f / 64.f);
            float rstd = rsqrtf(sq * (1.f / 64.f) - mu * mu + 1e-5f);
#pragma unroll
            for (int cc = 0; cc < 4; cc++) {
                int c = qq * 4 + cc;
                float v = syn[tl * 66 + c];
                sxa[tl * 72 + c] = __float2bfloat16((v - mu) * rstd * lw[c] + lb[c]);
            }
        }
        __syncthreads();
        {   // fc1: mma m16 x n32 per warp (4 jj)
            float acc[4][4];
#pragma unroll
            for (int jj = 0; jj < 4; jj++)
#pragma unroll
                for (int d = 0; d < 4; d++) acc[jj][d] = 0.f;
#pragma unroll
            for (int kk = 0; kk < 4; kk++) {
                int kbv = kk * 16;
                unsigned a0 = *(const unsigned*)(sxa + r0 * 72 + kbv + tt * 2);
                unsigned a1 = *(const unsigned*)(sxa + r1 * 72 + kbv + tt * 2);
                unsigned a2 = *(const unsigned*)(sxa + r0 * 72 + kbv + 8 + tt * 2);
                unsigned a3 = *(const unsigned*)(sxa + r1 * 72 + kbv + 8 + tt * 2);
#pragma unroll
                for (int jj = 0; jj < 4; jj++) {
                    int nn = ngrp * 32 + jj * 8 + g;
                    unsigned b0 = *(const unsigned*)(w1s + nn * 72 + kbv + tt * 2);
                    unsigned b1v = *(const unsigned*)(w1s + nn * 72 + kbv + 8 + tt * 2);
                    mma16816(acc[jj], a0, a1, a2, a3, b0, b1v);
                }
            }
#pragma unroll
            for (int jj = 0; jj < 4; jj++) {
                int c0 = ngrp * 32 + jj * 8 + tt * 2;
                float v00 = acc[jj][0] + sb1[c0];
                float v01 = acc[jj][1] + sb1[c0 + 1];
                float v10 = acc[jj][2] + sb1[c0];
                float v11 = acc[jj][3] + sb1[c0 + 1];
                v00 = 0.5f * v00 * (1.f + erff(v00 * 0.70710678f));
                v01 = 0.5f * v01 * (1.f + erff(v01 * 0.70710678f));
                v10 = 0.5f * v10 * (1.f + erff(v10 * 0.70710678f));
                v11 = 0.5f * v11 * (1.f + erff(v11 * 0.70710678f));
                *(__nv_bfloat162*)(sh + r0 * 264 + c0) = __floats2bfloat162_rn(v00, v01);
                *(__nv_bfloat162*)(sh + r1 * 264 + c0) = __floats2bfloat162_rn(v10, v11);
            }
        }
        __syncthreads();
        {   // fc2: mma m16 x n8 per warp
            float acc[4] = {0.f, 0.f, 0.f, 0.f};
            int nn = ngrp * 8 + g;
#pragma unroll 4
            for (int kk = 0; kk < 16; kk++) {
                int kbv = kk * 16;
                unsigned a0 = *(const unsigned*)(sh + r0 * 264 + kbv + tt * 2);
                unsigned a1 = *(const unsigned*)(sh + r1 * 264 + kbv + tt * 2);
                unsigned a2 = *(const unsigned*)(sh + r0 * 264 + kbv + 8 + tt * 2);
                unsigned a3 = *(const unsigned*)(sh + r1 * 264 + kbv + 8 + tt * 2);
                unsigned b0 = *(const unsigned*)(w2s + nn * 264 + kbv + tt * 2);
                unsigned b1v = *(const unsigned*)(w2s + nn * 264 + kbv + 8 + tt * 2);
                mma16816(acc, a0, a1, a2, a3, b0, b1v);
            }
            int c0 = ngrp * 8 + tt * 2;
            syn[r0 * 66 + c0]     = acc[0] + sb2[c0]     + syn[r0 * 66 + c0];
            syn[r0 * 66 + c0 + 1] = acc[1] + sb2[c0 + 1] + syn[r0 * 66 + c0 + 1];
            syn[r1 * 66 + c0]     = acc[2] + sb2[c0]     + syn[r1 * 66 + c0];
            syn[r1 * 66 + c0 + 1] = acc[3] + sb2[c0 + 1] + syn[r1 * 66 + c0 + 1];
        }
        __syncthreads();
        {   // coalesced NCHW write: 32 consecutive ij per c
            int tl = tid & 31;
#pragma unroll
            for (int p = 0; p < 4; p++) {
                int c = (tid >> 5) + (p << 4);
                out[(size_t)n * 262144 + (size_t)c * 4096 + ij0 + tl] = syn[tl * 66 + c];
            }
        }
        __syncthreads();
    }
}

// ---------------- launch ----------------
extern "C" void kernel_launch(void* const* d_in, const int* in_sizes, int n_in,
                              void* d_out, int out_size) {
    const float* x      = (const float*)d_in[0];
    const float* gn_w   = (const float*)d_in[1];
    const float* gn_b   = (const float*)d_in[2];
    const float* qkv_w  = (const float*)d_in[3];
    const float* qkv_b  = (const float*)d_in[4];
    const float* rpb    = (const float*)d_in[5];
    const float* proj_w = (const float*)d_in[6];
    const float* proj_b = (const float*)d_in[7];
    const float* ln_w   = (const float*)d_in[8];
    const float* ln_b   = (const float*)d_in[9];
    const float* fc1_w  = (const float*)d_in[10];
    const float* fc1_b  = (const float*)d_in[11];
    const float* fc2_w  = (const float*)d_in[12];
    const float* fc2_b  = (const float*)d_in[13];
    float* out = (float*)d_out;

    size_t sm_qkv  = 38144;                       // -> 5 co-resident blocks
    size_t sm_attn = (size_t)196 * PB * 2 * 2;    // 56448 -> 4 blocks/SM
    size_t sm_proj = 35840;                       // -> 6 co-resident blocks
    size_t sm_mlp  = 101888;                      // -> 2 blocks/SM

    cudaFuncSetAttribute(k_qkv,  cudaFuncAttributeMaxDynamicSharedMemorySize, (int)sm_qkv);
    cudaFuncSetAttribute(k_attn, cudaFuncAttributeMaxDynamicSharedMemorySize, (int)sm_attn);
    cudaFuncSetAttribute(k_proj, cudaFuncAttributeMaxDynamicSharedMemorySize, (int)sm_proj);
    cudaFuncSetAttribute(k_mlp,  cudaFuncAttributeMaxDynamicSharedMemorySize, (int)sm_mlp);

    k_stats1<<<256, 256>>>(x);
    k_qkv <<<512, 128, sm_qkv>>>(x, gn_w, gn_b, qkv_w, qkv_b);
    k_attn<<<512, 256, sm_attn>>>(rpb);
    k_proj<<<512, 128, sm_proj>>>(x, proj_w, proj_b);
    k_mlp <<<256, 512, sm_mlp>>>(ln_w, ln_b, fc1_w, fc1_b, fc2_w, fc2_b, out);
}

// round 13
// speedup vs baseline: 1.1042x; 1.1042x over previous
#include <cuda_runtime.h>
#include <cuda_bf16.h>
#include <math.h>

#define NSAMP 8
#define NTOK  32768

typedef unsigned long long ull;

// ---------------- helpers ----------------
__device__ __forceinline__ void fma2(ull& d, ull a, ull b) {
    asm("fma.rn.f32x2 %0, %1, %2, %0;" : "+l"(d) : "l"(a), "l"(b));
}
__device__ __forceinline__ ull b2p(unsigned u) {
    unsigned lo = u << 16, hi = u & 0xffff0000u;
    ull r; asm("mov.b64 %0, {%1,%2};" : "=l"(r) : "r"(lo), "r"(hi));
    return r;
}
__device__ __forceinline__ ull dup2(float e) {
    ull r; asm("mov.b64 %0, {%1,%1};" : "=l"(r) : "f"(e));
    return r;
}
__device__ __forceinline__ float2 up2(ull v) {
    float2 f;
    asm("mov.b64 {%0,%1}, %2;" : "=f"(f.x), "=f"(f.y) : "l"(v));
    return f;
}
__device__ __forceinline__ __nv_bfloat162 asbf2(unsigned u) {
    return *reinterpret_cast<__nv_bfloat162*>(&u);
}
__device__ __forceinline__ unsigned asu(__nv_bfloat162 v) {
    return *reinterpret_cast<unsigned*>(&v);
}

// ---------------- mma.sync m16n8k16 bf16 ----------------
__device__ __forceinline__ void mma16816(float* d, unsigned a0, unsigned a1,
                                         unsigned a2, unsigned a3,
                                         unsigned b0, unsigned b1) {
    asm("mma.sync.aligned.m16n8k16.row.col.f32.bf16.bf16.f32 "
        "{%0,%1,%2,%3}, {%4,%5,%6,%7}, {%8,%9}, {%0,%1,%2,%3};"
        : "+f"(d[0]), "+f"(d[1]), "+f"(d[2]), "+f"(d[3])
        : "r"(a0), "r"(a1), "r"(a2), "r"(a3), "r"(b0), "r"(b1));
}

// ---------------- scratch ----------------
__device__ float g_part[256][2];
__device__ __nv_bfloat16 g_qb[NTOK * 64];
__device__ __nv_bfloat16 g_kb[NTOK * 64];
__device__ __nv_bfloat16 g_vb[NTOK * 64];
__device__ float g_y[NTOK * 64];

// ---------------- K1: per-sample partial sum / sumsq ----------------
__global__ void k_stats1(const float* __restrict__ x) {
    __shared__ float rs_[256], rq_[256];
    int b = blockIdx.x;
    int n = b >> 5, ch = b & 31;
    const float4* p = (const float4*)(x + (size_t)n * 262144 + (size_t)ch * 8192);
    float s = 0.f, sq = 0.f;
#pragma unroll
    for (int i = 0; i < 8; i++) {
        float4 v = p[threadIdx.x + i * 256];
        s  += v.x + v.y + v.z + v.w;
        sq += v.x * v.x + v.y * v.y + v.z * v.z + v.w * v.w;
    }
    rs_[threadIdx.x] = s; rq_[threadIdx.x] = sq;
    __syncthreads();
    for (int st = 128; st > 0; st >>= 1) {
        if (threadIdx.x < st) {
            rs_[threadIdx.x] += rs_[threadIdx.x + st];
            rq_[threadIdx.x] += rq_[threadIdx.x + st];
        }
        __syncthreads();
    }
    if (threadIdx.x == 0) { g_part[b][0] = rs_[0]; g_part[b][1] = rq_[0]; }
}

// ---------------- K3: stats-finalize + norm + QKV (64->192) via bf16 mma ----------------
__global__ __launch_bounds__(256) void k_qkv(const float* __restrict__ x,
                      const float* __restrict__ gw, const float* __restrict__ gb,
                      const float* __restrict__ qkvw, const float* __restrict__ qkvb) {
    extern __shared__ __align__(16) char smraw[];
    __nv_bfloat16* sxa = (__nv_bfloat16*)smraw;           // 128*76 (19456B)
    __nv_bfloat16* sw  = (__nv_bfloat16*)(smraw + 19456); // 192*72 (27648B)
    float* sb = (float*)(smraw + 47104);                  // 192
    __shared__ float s_mu, s_rs;
    int tid = threadIdx.x;
    int t0 = blockIdx.x * 128;
    int n = t0 >> 12, ij0 = t0 & 4095;
    for (int i = tid; i < 6144; i += 256) {
        float2 wv = ((const float2*)qkvw)[i];
        int r = i >> 5, c2 = (i & 31) * 2;
        *(__nv_bfloat162*)(sw + r * 72 + c2) = __floats2bfloat162_rn(wv.x, wv.y);
    }
    if (tid < 192) sb[tid] = qkvb[tid];
    if (tid < 32) {   // per-sample stats finalize
        float s  = g_part[n * 32 + tid][0];
        float sq = g_part[n * 32 + tid][1];
#pragma unroll
        for (int st = 16; st > 0; st >>= 1) {
            s  += __shfl_xor_sync(0xffffffffu, s, st);
            sq += __shfl_xor_sync(0xffffffffu, sq, st);
        }
        if (tid == 0) {
            float mu  = s * (1.f / 262144.f);
            float var = sq * (1.f / 262144.f) - mu * mu;
            s_mu = mu;
            s_rs = rsqrtf(var + 1e-5f);
        }
    }
    __syncthreads();
    float mu = s_mu, rs = s_rs;
    {
        int tl = tid & 127, cb = tid >> 7;
#pragma unroll
        for (int p = 0; p < 32; p++) {
            int c = cb + (p << 1);
            float xv = x[(size_t)n * 262144 + (size_t)c * 4096 + ij0 + tl];
            sxa[tl * 76 + c] = __float2bfloat16((xv - mu) * rs * gw[c] + gb[c]);
        }
    }
    __syncthreads();
    int lane = tid & 31, wrp = tid >> 5;
    int g = lane >> 2, tt = lane & 3;
    int r0 = wrp * 16 + g, r1 = r0 + 8;
    unsigned a0[4], a1[4], a2[4], a3[4];
#pragma unroll
    for (int kk = 0; kk < 4; kk++) {
        int kbv = kk * 16;
        a0[kk] = *(const unsigned*)(sxa + r0 * 76 + kbv + tt * 2);
        a1[kk] = *(const unsigned*)(sxa + r1 * 76 + kbv + tt * 2);
        a2[kk] = *(const unsigned*)(sxa + r0 * 76 + kbv + 8 + tt * 2);
        a3[kk] = *(const unsigned*)(sxa + r1 * 76 + kbv + 8 + tt * 2);
    }
    size_t tok0 = (size_t)(t0 + r0) * 64, tok1 = (size_t)(t0 + r1) * 64;
#pragma unroll
    for (int jj = 0; jj < 24; jj++) {
        int nn = jj * 8 + g;
        float acc[4] = {0.f, 0.f, 0.f, 0.f};
#pragma unroll
        for (int kk = 0; kk < 4; kk++) {
            unsigned b0 = *(const unsigned*)(sw + nn * 72 + kk * 16 + tt * 2);
            unsigned b1 = *(const unsigned*)(sw + nn * 72 + kk * 16 + 8 + tt * 2);
            mma16816(acc, a0[kk], a1[kk], a2[kk], a3[kk], b0, b1);
        }
        int f0 = jj * 8 + tt * 2;
        float e00 = acc[0] + sb[f0], e01 = acc[1] + sb[f0 + 1];
        float e10 = acc[2] + sb[f0], e11 = acc[3] + sb[f0 + 1];
        if (f0 < 64) {
            *(__nv_bfloat162*)(g_qb + tok0 + f0) = __floats2bfloat162_rn(e00 * 0.25f, e01 * 0.25f);
            *(__nv_bfloat162*)(g_qb + tok1 + f0) = __floats2bfloat162_rn(e10 * 0.25f, e11 * 0.25f);
        } else if (f0 < 128) {
            *(__nv_bfloat162*)(g_kb + tok0 + f0 - 64) = __floats2bfloat162_rn(e00, e01);
            *(__nv_bfloat162*)(g_kb + tok1 + f0 - 64) = __floats2bfloat162_rn(e10, e11);
        } else {
            *(__nv_bfloat162*)(g_vb + tok0 + f0 - 128) = __floats2bfloat162_rn(e00, e01);
            *(__nv_bfloat162*)(g_vb + tok1 + f0 - 128) = __floats2bfloat162_rn(e10, e11);
        }
    }
}

// ---------------- K4: fused 7x7 attention + out-proj + residual ----------------
// phase 1: attention (K/V halo in smem); phase 2: reuse K/V smem for ao/weights/x,
// proj mma + residual -> g_y.  smem 56704B -> 4 blocks/SM.
#define WMX 14
#define PB  72
__global__ __launch_bounds__(256, 4) void k_attn(const float* __restrict__ rpb,
                       const float* __restrict__ x,
                       const float* __restrict__ pw, const float* __restrict__ pb) {
    extern __shared__ __align__(16) char smraw[];
    __nv_bfloat16* skb = (__nv_bfloat16*)smraw;           // 196*72 (28224B)
    __nv_bfloat16* svb = skb + 196 * PB;                  // 196*72 (28224B)
    float* sbp = (float*)(smraw + 56448);                 // 64 (256B)
    // phase-2 aliases (valid after post-AV sync):
    __nv_bfloat16* sa = (__nv_bfloat16*)smraw;            // 64*72 bf16 (9216B)
    __nv_bfloat16* sw = (__nv_bfloat16*)(smraw + 9216);   // 64*72 bf16 (9216B)
    float* sxr = (float*)(smraw + 28224);                 // 64*66 f32 (16896B)

    int tid = threadIdx.x, b = blockIdx.x;
    int n = b >> 6, t = b & 63;
    int i0 = (t >> 3) << 3, j0 = (t & 7) << 3;
    if (tid < 64) sbp[tid] = pb[tid];
    int rlo = max(i0 - 3, 0), rhi = min(i0 + 10, 63);
    int clo = max(j0 - 3, 0), chi = min(j0 + 10, 63);
    int nr = rhi - rlo + 1, nc = chi - clo + 1;
    int tot = nr * nc * 8;
    for (int idx = tid; idx < tot; idx += 256) {
        int c8 = idx & 7, p = idx >> 3;
        int lr = p / nc, lc = p - lr * nc;
        size_t gt = ((size_t)(n << 12) + ((rlo + lr) << 6) + (clo + lc)) * 64;
        uint4 kv = ((const uint4*)(g_kb + gt))[c8];
        uint4 vv = ((const uint4*)(g_vb + gt))[c8];
        int pp = lr * WMX + lc;
        ((uint4*)(skb + pp * PB))[c8] = kv;
        ((uint4*)(svb + pp * PB))[c8] = vv;
    }
    __syncthreads();

    int h = tid >> 6, q = tid & 63;
    int qi = q >> 3, qj = q & 7;
    int i = i0 + qi, j = j0 + qj;
    int sh_ = min(max(i - 3, 0), 57), sw_ = min(max(j - 3, 0), 57);
    int lsh = sh_ - rlo, lsw = sw_ - clo;
    int bh = i - sh_ + 6, bw = j - sw_ + 6;
    size_t tok = (size_t)(n << 12) + (i << 6) + j;
    const uint4* qp = (const uint4*)(g_qb + tok * 64 + h * 16);
    uint4 Q0 = qp[0], Q1 = qp[1];
    __nv_bfloat162 qh[8];
    qh[0] = asbf2(Q0.x); qh[1] = asbf2(Q0.y); qh[2] = asbf2(Q0.z); qh[3] = asbf2(Q0.w);
    qh[4] = asbf2(Q1.x); qh[5] = asbf2(Q1.y); qh[6] = asbf2(Q1.z); qh[7] = asbf2(Q1.w);
    const __nv_bfloat16* kb = skb + (lsh * WMX + lsw) * PB + h * 16;
    const __nv_bfloat16* vb = svb + (lsh * WMX + lsw) * PB + h * 16;
    const float* rbg = rpb + h * 169 + bh * 13 + bw;
    const __nv_bfloat162 hz = __floats2bfloat162_rn(0.f, 0.f);
    ull vacc[8] = {};
    float ssum = 0.f;
    for (int ah = 0; ah < 7; ah++) {
#pragma unroll
        for (int aw = 0; aw < 7; aw++) {
            int po = (ah * WMX + aw) * PB;
            const uint4* kp = (const uint4*)(kb + po);
            uint4 A = kp[0], B = kp[1];
            __nv_bfloat162 ac0 = hz, ac1 = hz;
            ac0 = __hfma2(qh[0], asbf2(A.x), ac0);
            ac1 = __hfma2(qh[1], asbf2(A.y), ac1);
            ac0 = __hfma2(qh[2], asbf2(A.z), ac0);
            ac1 = __hfma2(qh[3], asbf2(A.w), ac1);
            ac0 = __hfma2(qh[4], asbf2(B.x), ac0);
            ac1 = __hfma2(qh[5], asbf2(B.y), ac1);
            ac0 = __hfma2(qh[6], asbf2(B.z), ac0);
            ac1 = __hfma2(qh[7], asbf2(B.w), ac1);
            __nv_bfloat162 hs = __hadd2(ac0, ac1);
            float s = __bfloat162float(__low2bfloat16(hs))
                    + __bfloat162float(__high2bfloat16(hs))
                    + __ldg(rbg - (ah * 13 + aw));
            float e = __expf(s);
            ssum += e;
            ull e2 = dup2(e);
            const uint4* vp = (const uint4*)(vb + po);
            uint4 VA = vp[0], VB = vp[1];
            fma2(vacc[0], e2, b2p(VA.x));
            fma2(vacc[1], e2, b2p(VA.y));
            fma2(vacc[2], e2, b2p(VA.z));
            fma2(vacc[3], e2, b2p(VA.w));
            fma2(vacc[4], e2, b2p(VB.x));
            fma2(vacc[5], e2, b2p(VB.y));
            fma2(vacc[6], e2, b2p(VB.z));
            fma2(vacc[7], e2, b2p(VB.w));
        }
    }
    float inv = __fdividef(1.f, ssum);
    unsigned ob[8];
#pragma unroll
    for (int d = 0; d < 8; d++) {
        float2 f = up2(vacc[d]);
        ob[d] = asu(__floats2bfloat162_rn(f.x * inv, f.y * inv));
    }
    __syncthreads();   // all K/V reads done; smem now reusable

    // ---- phase 2: out-proj + residual ----
    *(uint4*)(sa + q * 72 + h * 16)     = make_uint4(ob[0], ob[1], ob[2], ob[3]);
    *(uint4*)(sa + q * 72 + h * 16 + 8) = make_uint4(ob[4], ob[5], ob[6], ob[7]);
    for (int idx = tid; idx < 2048; idx += 256) {         // proj weights (L2-hot)
        float2 wv = ((const float2*)pw)[idx];
        int r = idx >> 5, c2 = (idx & 31) * 2;
        *(__nv_bfloat162*)(sw + r * 72 + c2) = __floats2bfloat162_rn(wv.x, wv.y);
    }
    for (int idx = tid; idx < 4096; idx += 256) {         // residual x (NCHW)
        int c = idx >> 6, lt = idx & 63;
        sxr[lt * 66 + c] =
            x[(size_t)n * 262144 + (size_t)c * 4096 + ((i0 + (lt >> 3)) << 6) + j0 + (lt & 7)];
    }
    __syncthreads();

    int lane = tid & 31, wrp = tid >> 5;                  // 8 warps: 4 m-tiles x 2 n-halves
    int g = lane >> 2, tt = lane & 3;
    int mi = wrp & 3, nh = wrp >> 2;
    int r0 = mi * 16 + g, r1 = r0 + 8;
    unsigned a0[4], a1[4], a2[4], a3[4];
#pragma unroll
    for (int kk = 0; kk < 4; kk++) {
        int kbv = kk * 16;
        a0[kk] = *(const unsigned*)(sa + r0 * 72 + kbv + tt * 2);
        a1[kk] = *(const unsigned*)(sa + r1 * 72 + kbv + tt * 2);
        a2[kk] = *(const unsigned*)(sa + r0 * 72 + kbv + 8 + tt * 2);
        a3[kk] = *(const unsigned*)(sa + r1 * 72 + kbv + 8 + tt * 2);
    }
    size_t gt0 = (size_t)((n << 12) + ((i0 + (r0 >> 3)) << 6) + j0 + (r0 & 7)) * 64;
    size_t gt1 = (size_t)((n << 12) + ((i0 + (r1 >> 3)) << 6) + j0 + (r1 & 7)) * 64;
#pragma unroll
    for (int jj = 0; jj < 4; jj++) {
        int nn = nh * 32 + jj * 8 + g;
        float acc[4] = {0.f, 0.f, 0.f, 0.f};
#pragma unroll
        for (int kk = 0; kk < 4; kk++) {
            unsigned b0 = *(const unsigned*)(sw + nn * 72 + kk * 16 + tt * 2);
            unsigned b1 = *(const unsigned*)(sw + nn * 72 + kk * 16 + 8 + tt * 2);
            mma16816(acc, a0[kk], a1[kk], a2[kk], a3[kk], b0, b1);
        }
        int c0 = nh * 32 + jj * 8 + tt * 2;
        *(float2*)(g_y + gt0 + c0) = make_float2(
            acc[0] + sbp[c0] + sxr[r0 * 66 + c0],
            acc[1] + sbp[c0 + 1] + sxr[r0 * 66 + c0 + 1]);
        *(float2*)(g_y + gt1 + c0) = make_float2(
            acc[2] + sbp[c0] + sxr[r1 * 66 + c0],
            acc[3] + sbp[c0 + 1] + sxr[r1 * 66 + c0 + 1]);
    }
}

// ---------------- K6: LN + fc1 + GELU + fc2 + residual + NCHW ----------------
__global__ __launch_bounds__(512, 2) void k_mlp(const float* __restrict__ lw, const float* __restrict__ lb,
                      const float* __restrict__ w1, const float* __restrict__ b1,
                      const float* __restrict__ w2, const float* __restrict__ b2,
                      float* __restrict__ out) {
    extern __shared__ __align__(16) char smraw[];
    float* syn = (float*)smraw;                           // 32*66 f32  (8448B)
    __nv_bfloat16* sxa = (__nv_bfloat16*)(smraw + 8448);  // 32*72     (4608B)
    __nv_bfloat16* w1s = (__nv_bfloat16*)(smraw + 13056); // 256*72    (36864B)
    __nv_bfloat16* w2s = (__nv_bfloat16*)(smraw + 49920); // 64*264    (33792B)
    __nv_bfloat16* sh  = (__nv_bfloat16*)(smraw + 83712); // 32*264    (16896B)
    float* sb1 = (float*)(smraw + 100608);                // 256
    float* sb2 = (float*)(smraw + 101632);                // 64
    int tid = threadIdx.x;
    for (int i = tid; i < 16384; i += 512)
        w1s[(i >> 6) * 72 + (i & 63)] = __float2bfloat16(w1[i]);
    for (int i = tid; i < 16384; i += 512)
        w2s[(i >> 8) * 264 + (i & 255)] = __float2bfloat16(w2[i]);
    if (tid < 256) sb1[tid] = b1[tid];
    if (tid < 64)  sb2[tid] = b2[tid];
    __syncthreads();

    int lane = tid & 31, wrp = tid >> 5;           // 16 warps
    int g = lane >> 2, tt = lane & 3;
    int mi = wrp & 1, ngrp = wrp >> 1;             // 2 m-tiles x 8 n-groups
    int r0 = mi * 16 + g, r1 = r0 + 8;

    for (int it = 0; it < 4; it++) {
        int t0 = blockIdx.x * 128 + it * 32;
        int n = t0 >> 12, ij0 = t0 & 4095;
        for (int i = tid; i < 2048; i += 512)
            syn[(i >> 6) * 66 + (i & 63)] = g_y[(size_t)t0 * 64 + i];
        __syncthreads();
        {   // LayerNorm -> sxa bf16
            int tl = tid >> 4, qq = tid & 15;
            float s = 0.f, sq = 0.f;
#pragma unroll
            for (int cc = 0; cc < 4; cc++) {
                float v = syn[tl * 66 + qq * 4 + cc];
                s += v; sq += v * v;
            }
#pragma unroll
            for (int st = 1; st < 16; st <<= 1) {
                s  += __shfl_xor_sync(0xffffffffu, s, st);
                sq += __shfl_xor_sync(0xffffffffu, sq, st);
            }
            float mu = s * (1.f / 64.f);
            float rstd = rsqrtf(sq * (1.f / 64.f) - mu * mu + 1e-5f);
#pragma unroll
            for (int cc = 0; cc < 4; cc++) {
                int c = qq * 4 + cc;
                float v = syn[tl * 66 + c];
                sxa[tl * 72 + c] = __float2bfloat16((v - mu) * rstd * lw[c] + lb[c]);
            }
        }
        __syncthreads();
        {   // fc1: mma m16 x n32 per warp
            float acc[4][4];
#pragma unroll
            for (int jj = 0; jj < 4; jj++)
#pragma unroll
                for (int d = 0; d < 4; d++) acc[jj][d] = 0.f;
#pragma unroll
            for (int kk = 0; kk < 4; kk++) {
                int kbv = kk * 16;
                unsigned a0 = *(const unsigned*)(sxa + r0 * 72 + kbv + tt * 2);
                unsigned a1 = *(const unsigned*)(sxa + r1 * 72 + kbv + tt * 2);
                unsigned a2 = *(const unsigned*)(sxa + r0 * 72 + kbv + 8 + tt * 2);
                unsigned a3 = *(const unsigned*)(sxa + r1 * 72 + kbv + 8 + tt * 2);
#pragma unroll
                for (int jj = 0; jj < 4; jj++) {
                    int nn = ngrp * 32 + jj * 8 + g;
                    unsigned b0 = *(const unsigned*)(w1s + nn * 72 + kbv + tt * 2);
                    unsigned b1v = *(const unsigned*)(w1s + nn * 72 + kbv + 8 + tt * 2);
                    mma16816(acc[jj], a0, a1, a2, a3, b0, b1v);
                }
            }
#pragma unroll
            for (int jj = 0; jj < 4; jj++) {
                int c0 = ngrp * 32 + jj * 8 + tt * 2;
                float v00 = acc[jj][0] + sb1[c0];
                float v01 = acc[jj][1] + sb1[c0 + 1];
                float v10 = acc[jj][2] + sb1[c0];
                float v11 = acc[jj][3] + sb1[c0 + 1];
                v00 = 0.5f * v00 * (1.f + erff(v00 * 0.70710678f));
                v01 = 0.5f * v01 * (1.f + erff(v01 * 0.70710678f));
                v10 = 0.5f * v10 * (1.f + erff(v10 * 0.70710678f));
                v11 = 0.5f * v11 * (1.f + erff(v11 * 0.70710678f));
                *(__nv_bfloat162*)(sh + r0 * 264 + c0) = __floats2bfloat162_rn(v00, v01);
                *(__nv_bfloat162*)(sh + r1 * 264 + c0) = __floats2bfloat162_rn(v10, v11);
            }
        }
        __syncthreads();
        {   // fc2: mma m16 x n8 per warp
            float acc[4] = {0.f, 0.f, 0.f, 0.f};
            int nn = ngrp * 8 + g;
#pragma unroll 4
            for (int kk = 0; kk < 16; kk++) {
                int kbv = kk * 16;
                unsigned a0 = *(const unsigned*)(sh + r0 * 264 + kbv + tt * 2);
                unsigned a1 = *(const unsigned*)(sh + r1 * 264 + kbv + tt * 2);
                unsigned a2 = *(const unsigned*)(sh + r0 * 264 + kbv + 8 + tt * 2);
                unsigned a3 = *(const unsigned*)(sh + r1 * 264 + kbv + 8 + tt * 2);
                unsigned b0 = *(const unsigned*)(w2s + nn * 264 + kbv + tt * 2);
                unsigned b1v = *(const unsigned*)(w2s + nn * 264 + kbv + 8 + tt * 2);
                mma16816(acc, a0, a1, a2, a3, b0, b1v);
            }
            int c0 = ngrp * 8 + tt * 2;
            syn[r0 * 66 + c0]     = acc[0] + sb2[c0]     + syn[r0 * 66 + c0];
            syn[r0 * 66 + c0 + 1] = acc[1] + sb2[c0 + 1] + syn[r0 * 66 + c0 + 1];
            syn[r1 * 66 + c0]     = acc[2] + sb2[c0]     + syn[r1 * 66 + c0];
            syn[r1 * 66 + c0 + 1] = acc[3] + sb2[c0 + 1] + syn[r1 * 66 + c0 + 1];
        }
        __syncthreads();
        {   // coalesced NCHW write
            int tl = tid & 31;
#pragma unroll
            for (int p = 0; p < 4; p++) {
                int c = (tid >> 5) + (p << 4);
                out[(size_t)n * 262144 + (size_t)c * 4096 + ij0 + tl] = syn[tl * 66 + c];
            }
        }
        __syncthreads();
    }
}

// ---------------- launch ----------------
extern "C" void kernel_launch(void* const* d_in, const int* in_sizes, int n_in,
                              void* d_out, int out_size) {
    const float* x      = (const float*)d_in[0];
    const float* gn_w   = (const float*)d_in[1];
    const float* gn_b   = (const float*)d_in[2];
    const float* qkv_w  = (const float*)d_in[3];
    const float* qkv_b  = (const float*)d_in[4];
    const float* rpb    = (const float*)d_in[5];
    const float* proj_w = (const float*)d_in[6];
    const float* proj_b = (const float*)d_in[7];
    const float* ln_w   = (const float*)d_in[8];
    const float* ln_b   = (const float*)d_in[9];
    const float* fc1_w  = (const float*)d_in[10];
    const float* fc1_b  = (const float*)d_in[11];
    const float* fc2_w  = (const float*)d_in[12];
    const float* fc2_b  = (const float*)d_in[13];
    float* out = (float*)d_out;

    size_t sm_qkv  = 47872;
    size_t sm_attn = 56704;    // skb+svb+bias -> 4 blocks/SM
    size_t sm_mlp  = 101888;   // -> 2 blocks/SM

    cudaFuncSetAttribute(k_qkv,  cudaFuncAttributeMaxDynamicSharedMemorySize, (int)sm_qkv);
    cudaFuncSetAttribute(k_attn, cudaFuncAttributeMaxDynamicSharedMemorySize, (int)sm_attn);
    cudaFuncSetAttribute(k_mlp,  cudaFuncAttributeMaxDynamicSharedMemorySize, (int)sm_mlp);

    k_stats1<<<256, 256>>>(x);
    k_qkv <<<256, 256, sm_qkv>>>(x, gn_w, gn_b, qkv_w, qkv_b);
    k_attn<<<512, 256, sm_attn>>>(rpb, x, proj_w, proj_b);
    k_mlp <<<256, 512, sm_mlp>>>(ln_w, ln_b, fc1_w, fc1_b, fc2_w, fc2_b, out);
}

// round 14
// speedup vs baseline: 1.1621x; 1.0525x over previous
#include <cuda_runtime.h>
#include <cuda_bf16.h>
#include <math.h>

#define NSAMP 8
#define NTOK  32768

typedef unsigned long long ull;

// ---------------- helpers ----------------
__device__ __forceinline__ void fma2(ull& d, ull a, ull b) {
    asm("fma.rn.f32x2 %0, %1, %2, %0;" : "+l"(d) : "l"(a), "l"(b));
}
__device__ __forceinline__ ull b2p(unsigned u) {
    unsigned lo = u << 16, hi = u & 0xffff0000u;
    ull r; asm("mov.b64 %0, {%1,%2};" : "=l"(r) : "r"(lo), "r"(hi));
    return r;
}
__device__ __forceinline__ ull dup2(float e) {
    ull r; asm("mov.b64 %0, {%1,%1};" : "=l"(r) : "f"(e));
    return r;
}
__device__ __forceinline__ float2 up2(ull v) {
    float2 f;
    asm("mov.b64 {%0,%1}, %2;" : "=f"(f.x), "=f"(f.y) : "l"(v));
    return f;
}
__device__ __forceinline__ __nv_bfloat162 asbf2(unsigned u) {
    return *reinterpret_cast<__nv_bfloat162*>(&u);
}
__device__ __forceinline__ unsigned asu(__nv_bfloat162 v) {
    return *reinterpret_cast<unsigned*>(&v);
}
__device__ __forceinline__ float gelu_f(float v) {
    float u = 0.7978845608f * v * (1.f + 0.044715f * v * v);
    float t; asm("tanh.approx.f32 %0, %1;" : "=f"(t) : "f"(u));
    return 0.5f * v * (1.f + t);
}

// ---------------- mma.sync m16n8k16 bf16 ----------------
__device__ __forceinline__ void mma16816(float* d, unsigned a0, unsigned a1,
                                         unsigned a2, unsigned a3,
                                         unsigned b0, unsigned b1) {
    asm("mma.sync.aligned.m16n8k16.row.col.f32.bf16.bf16.f32 "
        "{%0,%1,%2,%3}, {%4,%5,%6,%7}, {%8,%9}, {%0,%1,%2,%3};"
        : "+f"(d[0]), "+f"(d[1]), "+f"(d[2]), "+f"(d[3])
        : "r"(a0), "r"(a1), "r"(a2), "r"(a3), "r"(b0), "r"(b1));
}

// ---------------- scratch ----------------
__device__ float g_part[256][2];
__device__ __nv_bfloat16 g_qb[NTOK * 64];
__device__ __nv_bfloat16 g_kb[NTOK * 64];
__device__ __nv_bfloat16 g_vb[NTOK * 64];
__device__ float g_y[NTOK * 64];
// pre-converted bf16 weights
__device__ __nv_bfloat16 g_w1b[16384];   // fc1  [256][64]
__device__ __nv_bfloat16 g_w2b[16384];   // fc2  [64][256]
__device__ __nv_bfloat16 g_wqb[12288];   // qkv  [192][64]
__device__ __nv_bfloat16 g_wpb[4096];    // proj [64][64]

// ---------------- K0: weight pre-conversion (once per launch) ----------------
__global__ void k_prep(const float* __restrict__ w1, const float* __restrict__ w2,
                       const float* __restrict__ qw, const float* __restrict__ pw) {
    int i = blockIdx.x * 256 + threadIdx.x;        // 0..24575 (float2 units)
    const float* src; __nv_bfloat16* dst; int off;
    if (i < 8192)       { src = w1; dst = g_w1b; off = i; }
    else if (i < 16384) { src = w2; dst = g_w2b; off = i - 8192; }
    else if (i < 22528) { src = qw; dst = g_wqb; off = i - 16384; }
    else                { src = pw; dst = g_wpb; off = i - 22528; }
    float2 v = ((const float2*)src)[off];
    *(__nv_bfloat162*)(dst + off * 2) = __floats2bfloat162_rn(v.x, v.y);
}

// ---------------- K1: per-sample partial sum / sumsq ----------------
__global__ void k_stats1(const float* __restrict__ x) {
    __shared__ float rs_[256], rq_[256];
    int b = blockIdx.x;
    int n = b >> 5, ch = b & 31;
    const float4* p = (const float4*)(x + (size_t)n * 262144 + (size_t)ch * 8192);
    float s = 0.f, sq = 0.f;
#pragma unroll
    for (int i = 0; i < 8; i++) {
        float4 v = p[threadIdx.x + i * 256];
        s  += v.x + v.y + v.z + v.w;
        sq += v.x * v.x + v.y * v.y + v.z * v.z + v.w * v.w;
    }
    rs_[threadIdx.x] = s; rq_[threadIdx.x] = sq;
    __syncthreads();
    for (int st = 128; st > 0; st >>= 1) {
        if (threadIdx.x < st) {
            rs_[threadIdx.x] += rs_[threadIdx.x + st];
            rq_[threadIdx.x] += rq_[threadIdx.x + st];
        }
        __syncthreads();
    }
    if (threadIdx.x == 0) { g_part[b][0] = rs_[0]; g_part[b][1] = rq_[0]; }
}

// ---------------- K3: stats-finalize + norm + QKV (64->192) via bf16 mma ----------------
__global__ __launch_bounds__(256) void k_qkv(const float* __restrict__ x,
                      const float* __restrict__ gw, const float* __restrict__ gb,
                      const float* __restrict__ qkvb) {
    extern __shared__ __align__(16) char smraw[];
    __nv_bfloat16* sxa = (__nv_bfloat16*)smraw;           // 128*76 (19456B)
    __nv_bfloat16* sw  = (__nv_bfloat16*)(smraw + 19456); // 192*72 (27648B)
    float* sb = (float*)(smraw + 47104);                  // 192
    __shared__ float s_mu, s_rs;
    int tid = threadIdx.x;
    int t0 = blockIdx.x * 128;
    int n = t0 >> 12, ij0 = t0 & 4095;
    for (int i = tid; i < 1536; i += 256) {               // bf16 weights, uint4 copy
        int r = i >> 3, c8 = i & 7;
        *(uint4*)(sw + r * 72 + c8 * 8) = *(const uint4*)(g_wqb + r * 64 + c8 * 8);
    }
    if (tid < 192) sb[tid] = qkvb[tid];
    if (tid < 32) {
        float s  = g_part[n * 32 + tid][0];
        float sq = g_part[n * 32 + tid][1];
#pragma unroll
        for (int st = 16; st > 0; st >>= 1) {
            s  += __shfl_xor_sync(0xffffffffu, s, st);
            sq += __shfl_xor_sync(0xffffffffu, sq, st);
        }
        if (tid == 0) {
            float mu  = s * (1.f / 262144.f);
            float var = sq * (1.f / 262144.f) - mu * mu;
            s_mu = mu;
            s_rs = rsqrtf(var + 1e-5f);
        }
    }
    __syncthreads();
    float mu = s_mu, rs = s_rs;
    {
        int tl = tid & 127, cb = tid >> 7;
#pragma unroll
        for (int p = 0; p < 32; p++) {
            int c = cb + (p << 1);
            float xv = x[(size_t)n * 262144 + (size_t)c * 4096 + ij0 + tl];
            sxa[tl * 76 + c] = __float2bfloat16((xv - mu) * rs * gw[c] + gb[c]);
        }
    }
    __syncthreads();
    int lane = tid & 31, wrp = tid >> 5;
    int g = lane >> 2, tt = lane & 3;
    int r0 = wrp * 16 + g, r1 = r0 + 8;
    unsigned a0[4], a1[4], a2[4], a3[4];
#pragma unroll
    for (int kk = 0; kk < 4; kk++) {
        int kbv = kk * 16;
        a0[kk] = *(const unsigned*)(sxa + r0 * 76 + kbv + tt * 2);
        a1[kk] = *(const unsigned*)(sxa + r1 * 76 + kbv + tt * 2);
        a2[kk] = *(const unsigned*)(sxa + r0 * 76 + kbv + 8 + tt * 2);
        a3[kk] = *(const unsigned*)(sxa + r1 * 76 + kbv + 8 + tt * 2);
    }
    size_t tok0 = (size_t)(t0 + r0) * 64, tok1 = (size_t)(t0 + r1) * 64;
#pragma unroll
    for (int jj = 0; jj < 24; jj++) {
        int nn = jj * 8 + g;
        float acc[4] = {0.f, 0.f, 0.f, 0.f};
#pragma unroll
        for (int kk = 0; kk < 4; kk++) {
            unsigned b0 = *(const unsigned*)(sw + nn * 72 + kk * 16 + tt * 2);
            unsigned b1 = *(const unsigned*)(sw + nn * 72 + kk * 16 + 8 + tt * 2);
            mma16816(acc, a0[kk], a1[kk], a2[kk], a3[kk], b0, b1);
        }
        int f0 = jj * 8 + tt * 2;
        float e00 = acc[0] + sb[f0], e01 = acc[1] + sb[f0 + 1];
        float e10 = acc[2] + sb[f0], e11 = acc[3] + sb[f0 + 1];
        if (f0 < 64) {
            *(__nv_bfloat162*)(g_qb + tok0 + f0) = __floats2bfloat162_rn(e00 * 0.25f, e01 * 0.25f);
            *(__nv_bfloat162*)(g_qb + tok1 + f0) = __floats2bfloat162_rn(e10 * 0.25f, e11 * 0.25f);
        } else if (f0 < 128) {
            *(__nv_bfloat162*)(g_kb + tok0 + f0 - 64) = __floats2bfloat162_rn(e00, e01);
            *(__nv_bfloat162*)(g_kb + tok1 + f0 - 64) = __floats2bfloat162_rn(e10, e11);
        } else {
            *(__nv_bfloat162*)(g_vb + tok0 + f0 - 128) = __floats2bfloat162_rn(e00, e01);
            *(__nv_bfloat162*)(g_vb + tok1 + f0 - 128) = __floats2bfloat162_rn(e10, e11);
        }
    }
}

// ---------------- K4: fused 7x7 attention + out-proj + residual ----------------
#define WMX 14
#define PB  72
__global__ __launch_bounds__(256, 4) void k_attn(const float* __restrict__ rpb,
                       const float* __restrict__ x, const float* __restrict__ pb) {
    extern __shared__ __align__(16) char smraw[];
    __nv_bfloat16* skb = (__nv_bfloat16*)smraw;           // 196*72 (28224B)
    __nv_bfloat16* svb = skb + 196 * PB;                  // 196*72 (28224B)
    float* sbp = (float*)(smraw + 56448);                 // 64 (256B)
    // phase-2 aliases:
    __nv_bfloat16* sa = (__nv_bfloat16*)smraw;            // 64*72 bf16
    __nv_bfloat16* sw = (__nv_bfloat16*)(smraw + 9216);   // 64*72 bf16
    float* sxr = (float*)(smraw + 28224);                 // 64*66 f32

    int tid = threadIdx.x, b = blockIdx.x;
    int n = b >> 6, t = b & 63;
    int i0 = (t >> 3) << 3, j0 = (t & 7) << 3;
    if (tid < 64) sbp[tid] = pb[tid];
    int rlo = max(i0 - 3, 0), rhi = min(i0 + 10, 63);
    int clo = max(j0 - 3, 0), chi = min(j0 + 10, 63);
    int nr = rhi - rlo + 1, nc = chi - clo + 1;
    int tot = nr * nc * 8;
    for (int idx = tid; idx < tot; idx += 256) {
        int c8 = idx & 7, p = idx >> 3;
        int lr = p / nc, lc = p - lr * nc;
        size_t gt = ((size_t)(n << 12) + ((rlo + lr) << 6) + (clo + lc)) * 64;
        uint4 kv = ((const uint4*)(g_kb + gt))[c8];
        uint4 vv = ((const uint4*)(g_vb + gt))[c8];
        int pp = lr * WMX + lc;
        ((uint4*)(skb + pp * PB))[c8] = kv;
        ((uint4*)(svb + pp * PB))[c8] = vv;
    }
    __syncthreads();

    int h = tid >> 6, q = tid & 63;
    int qi = q >> 3, qj = q & 7;
    int i = i0 + qi, j = j0 + qj;
    int sh_ = min(max(i - 3, 0), 57), sw_ = min(max(j - 3, 0), 57);
    int lsh = sh_ - rlo, lsw = sw_ - clo;
    int bh = i - sh_ + 6, bw = j - sw_ + 6;
    size_t tok = (size_t)(n << 12) + (i << 6) + j;
    const uint4* qp = (const uint4*)(g_qb + tok * 64 + h * 16);
    uint4 Q0 = qp[0], Q1 = qp[1];
    __nv_bfloat162 qh[8];
    qh[0] = asbf2(Q0.x); qh[1] = asbf2(Q0.y); qh[2] = asbf2(Q0.z); qh[3] = asbf2(Q0.w);
    qh[4] = asbf2(Q1.x); qh[5] = asbf2(Q1.y); qh[6] = asbf2(Q1.z); qh[7] = asbf2(Q1.w);
    const __nv_bfloat16* kb = skb + (lsh * WMX + lsw) * PB + h * 16;
    const __nv_bfloat16* vb = svb + (lsh * WMX + lsw) * PB + h * 16;
    const float* rbg = rpb + h * 169 + bh * 13 + bw;
    const __nv_bfloat162 hz = __floats2bfloat162_rn(0.f, 0.f);
    ull vacc[8] = {};
    float ssum = 0.f;
    for (int ah = 0; ah < 7; ah++) {
#pragma unroll
        for (int aw = 0; aw < 7; aw++) {
            int po = (ah * WMX + aw) * PB;
            const uint4* kp = (const uint4*)(kb + po);
            uint4 A = kp[0], B = kp[1];
            __nv_bfloat162 ac0 = hz, ac1 = hz;
            ac0 = __hfma2(qh[0], asbf2(A.x), ac0);
            ac1 = __hfma2(qh[1], asbf2(A.y), ac1);
            ac0 = __hfma2(qh[2], asbf2(A.z), ac0);
            ac1 = __hfma2(qh[3], asbf2(A.w), ac1);
            ac0 = __hfma2(qh[4], asbf2(B.x), ac0);
            ac1 = __hfma2(qh[5], asbf2(B.y), ac1);
            ac0 = __hfma2(qh[6], asbf2(B.z), ac0);
            ac1 = __hfma2(qh[7], asbf2(B.w), ac1);
            __nv_bfloat162 hs = __hadd2(ac0, ac1);
            float s = __bfloat162float(__low2bfloat16(hs))
                    + __bfloat162float(__high2bfloat16(hs))
                    + __ldg(rbg - (ah * 13 + aw));
            float e = __expf(s);
            ssum += e;
            ull e2 = dup2(e);
            const uint4* vp = (const uint4*)(vb + po);
            uint4 VA = vp[0], VB = vp[1];
            fma2(vacc[0], e2, b2p(VA.x));
            fma2(vacc[1], e2, b2p(VA.y));
            fma2(vacc[2], e2, b2p(VA.z));
            fma2(vacc[3], e2, b2p(VA.w));
            fma2(vacc[4], e2, b2p(VB.x));
            fma2(vacc[5], e2, b2p(VB.y));
            fma2(vacc[6], e2, b2p(VB.z));
            fma2(vacc[7], e2, b2p(VB.w));
        }
    }
    float inv = __fdividef(1.f, ssum);
    unsigned ob[8];
#pragma unroll
    for (int d = 0; d < 8; d++) {
        float2 f = up2(vacc[d]);
        ob[d] = asu(__floats2bfloat162_rn(f.x * inv, f.y * inv));
    }
    __syncthreads();   // all K/V reads done; smem reusable

    // ---- phase 2: out-proj + residual ----
    *(uint4*)(sa + q * 72 + h * 16)     = make_uint4(ob[0], ob[1], ob[2], ob[3]);
    *(uint4*)(sa + q * 72 + h * 16 + 8) = make_uint4(ob[4], ob[5], ob[6], ob[7]);
    for (int idx = tid; idx < 512; idx += 256) {          // bf16 proj weights
        int r = idx >> 3, c8 = idx & 7;
        *(uint4*)(sw + r * 72 + c8 * 8) = *(const uint4*)(g_wpb + r * 64 + c8 * 8);
    }
    for (int idx = tid; idx < 4096; idx += 256) {         // residual x (NCHW)
        int c = idx >> 6, lt = idx & 63;
        sxr[lt * 66 + c] =
            x[(size_t)n * 262144 + (size_t)c * 4096 + ((i0 + (lt >> 3)) << 6) + j0 + (lt & 7)];
    }
    __syncthreads();

    int lane = tid & 31, wrp = tid >> 5;
    int g = lane >> 2, tt = lane & 3;
    int mi = wrp & 3, nh = wrp >> 2;
    int r0 = mi * 16 + g, r1 = r0 + 8;
    unsigned a0[4], a1[4], a2[4], a3[4];
#pragma unroll
    for (int kk = 0; kk < 4; kk++) {
        int kbv = kk * 16;
        a0[kk] = *(const unsigned*)(sa + r0 * 72 + kbv + tt * 2);
        a1[kk] = *(const unsigned*)(sa + r1 * 72 + kbv + tt * 2);
        a2[kk] = *(const unsigned*)(sa + r0 * 72 + kbv + 8 + tt * 2);
        a3[kk] = *(const unsigned*)(sa + r1 * 72 + kbv + 8 + tt * 2);
    }
    size_t gt0 = (size_t)((n << 12) + ((i0 + (r0 >> 3)) << 6) + j0 + (r0 & 7)) * 64;
    size_t gt1 = (size_t)((n << 12) + ((i0 + (r1 >> 3)) << 6) + j0 + (r1 & 7)) * 64;
#pragma unroll
    for (int jj = 0; jj < 4; jj++) {
        int nn = nh * 32 + jj * 8 + g;
        float acc[4] = {0.f, 0.f, 0.f, 0.f};
#pragma unroll
        for (int kk = 0; kk < 4; kk++) {
            unsigned b0 = *(const unsigned*)(sw + nn * 72 + kk * 16 + tt * 2);
            unsigned b1 = *(const unsigned*)(sw + nn * 72 + kk * 16 + 8 + tt * 2);
            mma16816(acc, a0[kk], a1[kk], a2[kk], a3[kk], b0, b1);
        }
        int c0 = nh * 32 + jj * 8 + tt * 2;
        *(float2*)(g_y + gt0 + c0) = make_float2(
            acc[0] + sbp[c0] + sxr[r0 * 66 + c0],
            acc[1] + sbp[c0 + 1] + sxr[r0 * 66 + c0 + 1]);
        *(float2*)(g_y + gt1 + c0) = make_float2(
            acc[2] + sbp[c0] + sxr[r1 * 66 + c0],
            acc[3] + sbp[c0 + 1] + sxr[r1 * 66 + c0 + 1]);
    }
}

// ---------------- K6: LN + fc1 + GELU(tanh) + fc2 + residual + NCHW ----------------
__global__ __launch_bounds__(512, 2) void k_mlp(const float* __restrict__ lw, const float* __restrict__ lb,
                      const float* __restrict__ b1, const float* __restrict__ b2,
                      float* __restrict__ out) {
    extern __shared__ __align__(16) char smraw[];
    float* syn = (float*)smraw;                           // 32*66 f32  (8448B)
    __nv_bfloat16* sxa = (__nv_bfloat16*)(smraw + 8448);  // 32*72     (4608B)
    __nv_bfloat16* w1s = (__nv_bfloat16*)(smraw + 13056); // 256*72    (36864B)
    __nv_bfloat16* w2s = (__nv_bfloat16*)(smraw + 49920); // 64*264    (33792B)
    __nv_bfloat16* sh  = (__nv_bfloat16*)(smraw + 83712); // 32*264    (16896B)
    float* sb1 = (float*)(smraw + 100608);                // 256
    float* sb2 = (float*)(smraw + 101632);                // 64
    int tid = threadIdx.x;
    for (int i = tid; i < 2048; i += 512) {               // fc1 bf16 [256][64]
        int r = i >> 3, c8 = i & 7;
        *(uint4*)(w1s + r * 72 + c8 * 8) = *(const uint4*)(g_w1b + r * 64 + c8 * 8);
    }
    for (int i = tid; i < 2048; i += 512) {               // fc2 bf16 [64][256]
        int r = i >> 5, c32 = i & 31;
        *(uint4*)(w2s + r * 264 + c32 * 8) = *(const uint4*)(g_w2b + r * 256 + c32 * 8);
    }
    if (tid < 256) sb1[tid] = b1[tid];
    if (tid < 64)  sb2[tid] = b2[tid];
    __syncthreads();

    int lane = tid & 31, wrp = tid >> 5;           // 16 warps
    int g = lane >> 2, tt = lane & 3;
    int mi = wrp & 1, ngrp = wrp >> 1;             // 2 m-tiles x 8 n-groups
    int r0 = mi * 16 + g, r1 = r0 + 8;

    for (int it = 0; it < 4; it++) {
        int t0 = blockIdx.x * 128 + it * 32;
        int n = t0 >> 12, ij0 = t0 & 4095;
        for (int i = tid; i < 2048; i += 512)
            syn[(i >> 6) * 66 + (i & 63)] = g_y[(size_t)t0 * 64 + i];
        __syncthreads();
        {   // LayerNorm -> sxa bf16
            int tl = tid >> 4, qq = tid & 15;
            float s = 0.f, sq = 0.f;
#pragma unroll
            for (int cc = 0; cc < 4; cc++) {
                float v = syn[tl * 66 + qq * 4 + cc];
                s += v; sq += v * v;
            }
#pragma unroll
            for (int st = 1; st < 16; st <<= 1) {
                s  += __shfl_xor_sync(0xffffffffu, s, st);
                sq += __shfl_xor_sync(0xffffffffu, sq, st);
            }
            float mu = s * (1.f / 64.f);
            float rstd = rsqrtf(sq * (1.f / 64.f) - mu * mu + 1e-5f);
#pragma unroll
            for (int cc = 0; cc < 4; cc++) {
                int c = qq * 4 + cc;
                float v = syn[tl * 66 + c];
                sxa[tl * 72 + c] = __float2bfloat16((v - mu) * rstd * lw[c] + lb[c]);
            }
        }
        __syncthreads();
        {   // fc1: mma m16 x n32 per warp + fast GELU
            float acc[4][4];
#pragma unroll
            for (int jj = 0; jj < 4; jj++)
#pragma unroll
                for (int d = 0; d < 4; d++) acc[jj][d] = 0.f;
#pragma unroll
            for (int kk = 0; kk < 4; kk++) {
                int kbv = kk * 16;
                unsigned a0 = *(const unsigned*)(sxa + r0 * 72 + kbv + tt * 2);
                unsigned a1 = *(const unsigned*)(sxa + r1 * 72 + kbv + tt * 2);
                unsigned a2 = *(const unsigned*)(sxa + r0 * 72 + kbv + 8 + tt * 2);
                unsigned a3 = *(const unsigned*)(sxa + r1 * 72 + kbv + 8 + tt * 2);
#pragma unroll
                for (int jj = 0; jj < 4; jj++) {
                    int nn = ngrp * 32 + jj * 8 + g;
                    unsigned b0 = *(const unsigned*)(w1s + nn * 72 + kbv + tt * 2);
                    unsigned b1v = *(const unsigned*)(w1s + nn * 72 + kbv + 8 + tt * 2);
                    mma16816(acc[jj], a0, a1, a2, a3, b0, b1v);
                }
            }
#pragma unroll
            for (int jj = 0; jj < 4; jj++) {
                int c0 = ngrp * 32 + jj * 8 + tt * 2;
                float v00 = gelu_f(acc[jj][0] + sb1[c0]);
                float v01 = gelu_f(acc[jj][1] + sb1[c0 + 1]);
                float v10 = gelu_f(acc[jj][2] + sb1[c0]);
                float v11 = gelu_f(acc[jj][3] + sb1[c0 + 1]);
                *(__nv_bfloat162*)(sh + r0 * 264 + c0) = __floats2bfloat162_rn(v00, v01);
                *(__nv_bfloat162*)(sh + r1 * 264 + c0) = __floats2bfloat162_rn(v10, v11);
            }
        }
        __syncthreads();
        {   // fc2: mma m16 x n8 per warp
            float acc[4] = {0.f, 0.f, 0.f, 0.f};
            int nn = ngrp * 8 + g;
#pragma unroll 4
            for (int kk = 0; kk < 16; kk++) {
                int kbv = kk * 16;
                unsigned a0 = *(const unsigned*)(sh + r0 * 264 + kbv + tt * 2);
                unsigned a1 = *(const unsigned*)(sh + r1 * 264 + kbv + tt * 2);
                unsigned a2 = *(const unsigned*)(sh + r0 * 264 + kbv + 8 + tt * 2);
                unsigned a3 = *(const unsigned*)(sh + r1 * 264 + kbv + 8 + tt * 2);
                unsigned b0 = *(const unsigned*)(w2s + nn * 264 + kbv + tt * 2);
                unsigned b1v = *(const unsigned*)(w2s + nn * 264 + kbv + 8 + tt * 2);
                mma16816(acc, a0, a1, a2, a3, b0, b1v);
            }
            int c0 = ngrp * 8 + tt * 2;
            syn[r0 * 66 + c0]     = acc[0] + sb2[c0]     + syn[r0 * 66 + c0];
            syn[r0 * 66 + c0 + 1] = acc[1] + sb2[c0 + 1] + syn[r0 * 66 + c0 + 1];
            syn[r1 * 66 + c0]     = acc[2] + sb2[c0]     + syn[r1 * 66 + c0];
            syn[r1 * 66 + c0 + 1] = acc[3] + sb2[c0 + 1] + syn[r1 * 66 + c0 + 1];
        }
        __syncthreads();
        {   // coalesced NCHW write
            int tl = tid & 31;
#pragma unroll
            for (int p = 0; p < 4; p++) {
                int c = (tid >> 5) + (p << 4);
                out[(size_t)n * 262144 + (size_t)c * 4096 + ij0 + tl] = syn[tl * 66 + c];
            }
        }
        __syncthreads();
    }
}

// ---------------- launch ----------------
extern "C" void kernel_launch(void* const* d_in, const int* in_sizes, int n_in,
                              void* d_out, int out_size) {
    const float* x      = (const float*)d_in[0];
    const float* gn_w   = (const float*)d_in[1];
    const float* gn_b   = (const float*)d_in[2];
    const float* qkv_w  = (const float*)d_in[3];
    const float* qkv_b  = (const float*)d_in[4];
    const float* rpb    = (const float*)d_in[5];
    const float* proj_w = (const float*)d_in[6];
    const float* proj_b = (const float*)d_in[7];
    const float* ln_w   = (const float*)d_in[8];
    const float* ln_b   = (const float*)d_in[9];
    const float* fc1_w  = (const float*)d_in[10];
    const float* fc1_b  = (const float*)d_in[11];
    const float* fc2_w  = (const float*)d_in[12];
    const float* fc2_b  = (const float*)d_in[13];
    float* out = (float*)d_out;

    size_t sm_qkv  = 47872;
    size_t sm_attn = 56704;    // -> 4 blocks/SM
    size_t sm_mlp  = 101888;   // -> 2 blocks/SM

    cudaFuncSetAttribute(k_qkv,  cudaFuncAttributeMaxDynamicSharedMemorySize, (int)sm_qkv);
    cudaFuncSetAttribute(k_attn, cudaFuncAttributeMaxDynamicSharedMemorySize, (int)sm_attn);
    cudaFuncSetAttribute(k_mlp,  cudaFuncAttributeMaxDynamicSharedMemorySize, (int)sm_mlp);

    k_prep  <<<96, 256>>>(fc1_w, fc2_w, qkv_w, proj_w);
    k_stats1<<<256, 256>>>(x);
    k_qkv <<<256, 256, sm_qkv>>>(x, gn_w, gn_b, qkv_b);
    k_attn<<<512, 256, sm_attn>>>(rpb, x, proj_b);
    k_mlp <<<256, 512, sm_mlp>>>(ln_w, ln_b, fc1_b, fc2_b, out);
}

// round 15
// speedup vs baseline: 1.1939x; 1.0274x over previous
#include <cuda_runtime.h>
#include <cuda_bf16.h>
#include <math.h>

#define NSAMP 8
#define NTOK  32768

typedef unsigned long long ull;

// ---------------- helpers ----------------
__device__ __forceinline__ void fma2(ull& d, ull a, ull b) {
    asm("fma.rn.f32x2 %0, %1, %2, %0;" : "+l"(d) : "l"(a), "l"(b));
}
__device__ __forceinline__ ull b2p(unsigned u) {
    unsigned lo = u << 16, hi = u & 0xffff0000u;
    ull r; asm("mov.b64 %0, {%1,%2};" : "=l"(r) : "r"(lo), "r"(hi));
    return r;
}
__device__ __forceinline__ ull dup2(float e) {
    ull r; asm("mov.b64 %0, {%1,%1};" : "=l"(r) : "f"(e));
    return r;
}
__device__ __forceinline__ float2 up2(ull v) {
    float2 f;
    asm("mov.b64 {%0,%1}, %2;" : "=f"(f.x), "=f"(f.y) : "l"(v));
    return f;
}
__device__ __forceinline__ __nv_bfloat162 asbf2(unsigned u) {
    return *reinterpret_cast<__nv_bfloat162*>(&u);
}
__device__ __forceinline__ unsigned asu(__nv_bfloat162 v) {
    return *reinterpret_cast<unsigned*>(&v);
}
__device__ __forceinline__ float gelu_f(float v) {
    float u = 0.7978845608f * v * (1.f + 0.044715f * v * v);
    float t; asm("tanh.approx.f32 %0, %1;" : "=f"(t) : "f"(u));
    return 0.5f * v * (1.f + t);
}

// ---------------- mma.sync m16n8k16 bf16 ----------------
__device__ __forceinline__ void mma16816(float* d, unsigned a0, unsigned a1,
                                         unsigned a2, unsigned a3,
                                         unsigned b0, unsigned b1) {
    asm("mma.sync.aligned.m16n8k16.row.col.f32.bf16.bf16.f32 "
        "{%0,%1,%2,%3}, {%4,%5,%6,%7}, {%8,%9}, {%0,%1,%2,%3};"
        : "+f"(d[0]), "+f"(d[1]), "+f"(d[2]), "+f"(d[3])
        : "r"(a0), "r"(a1), "r"(a2), "r"(a3), "r"(b0), "r"(b1));
}

// ---------------- scratch ----------------
__device__ float g_part[256][2];
__device__ __nv_bfloat16 g_qb[NTOK * 64];
__device__ __nv_bfloat16 g_kb[NTOK * 64];
__device__ __nv_bfloat16 g_vb[NTOK * 64];
__device__ float g_y[NTOK * 64];
__device__ __nv_bfloat16 g_w1b[16384];
__device__ __nv_bfloat16 g_w2b[16384];
__device__ __nv_bfloat16 g_wqb[12288];
__device__ __nv_bfloat16 g_wpb[4096];

// ---------------- K0: weight pre-conversion ----------------
__global__ void k_prep(const float* __restrict__ w1, const float* __restrict__ w2,
                       const float* __restrict__ qw, const float* __restrict__ pw) {
    int i = blockIdx.x * 256 + threadIdx.x;
    const float* src; __nv_bfloat16* dst; int off;
    if (i < 8192)       { src = w1; dst = g_w1b; off = i; }
    else if (i < 16384) { src = w2; dst = g_w2b; off = i - 8192; }
    else if (i < 22528) { src = qw; dst = g_wqb; off = i - 16384; }
    else                { src = pw; dst = g_wpb; off = i - 22528; }
    float2 v = ((const float2*)src)[off];
    *(__nv_bfloat162*)(dst + off * 2) = __floats2bfloat162_rn(v.x, v.y);
}

// ---------------- K1: per-sample partial sum / sumsq ----------------
__global__ void k_stats1(const float* __restrict__ x) {
    __shared__ float rs_[256], rq_[256];
    int b = blockIdx.x;
    int n = b >> 5, ch = b & 31;
    const float4* p = (const float4*)(x + (size_t)n * 262144 + (size_t)ch * 8192);
    float s = 0.f, sq = 0.f;
#pragma unroll
    for (int i = 0; i < 8; i++) {
        float4 v = p[threadIdx.x + i * 256];
        s  += v.x + v.y + v.z + v.w;
        sq += v.x * v.x + v.y * v.y + v.z * v.z + v.w * v.w;
    }
    rs_[threadIdx.x] = s; rq_[threadIdx.x] = sq;
    __syncthreads();
    for (int st = 128; st > 0; st >>= 1) {
        if (threadIdx.x < st) {
            rs_[threadIdx.x] += rs_[threadIdx.x + st];
            rq_[threadIdx.x] += rq_[threadIdx.x + st];
        }
        __syncthreads();
    }
    if (threadIdx.x == 0) { g_part[b][0] = rs_[0]; g_part[b][1] = rq_[0]; }
}

// ---------------- K3: stats-finalize + norm + QKV via bf16 mma ----------------
__global__ __launch_bounds__(256) void k_qkv(const float* __restrict__ x,
                      const float* __restrict__ gw, const float* __restrict__ gb,
                      const float* __restrict__ qkvb) {
    extern __shared__ __align__(16) char smraw[];
    __nv_bfloat16* sxa = (__nv_bfloat16*)smraw;           // 128*76
    __nv_bfloat16* sw  = (__nv_bfloat16*)(smraw + 19456); // 192*72
    float* sb = (float*)(smraw + 47104);                  // 192
    __shared__ float s_mu, s_rs;
    int tid = threadIdx.x;
    int t0 = blockIdx.x * 128;
    int n = t0 >> 12, ij0 = t0 & 4095;
    for (int i = tid; i < 1536; i += 256) {
        int r = i >> 3, c8 = i & 7;
        *(uint4*)(sw + r * 72 + c8 * 8) = *(const uint4*)(g_wqb + r * 64 + c8 * 8);
    }
    if (tid < 192) sb[tid] = qkvb[tid];
    if (tid < 32) {
        float s  = g_part[n * 32 + tid][0];
        float sq = g_part[n * 32 + tid][1];
#pragma unroll
        for (int st = 16; st > 0; st >>= 1) {
            s  += __shfl_xor_sync(0xffffffffu, s, st);
            sq += __shfl_xor_sync(0xffffffffu, sq, st);
        }
        if (tid == 0) {
            float mu  = s * (1.f / 262144.f);
            float var = sq * (1.f / 262144.f) - mu * mu;
            s_mu = mu;
            s_rs = rsqrtf(var + 1e-5f);
        }
    }
    __syncthreads();
    float mu = s_mu, rs = s_rs;
    {
        int tl = tid & 127, cb = tid >> 7;
#pragma unroll
        for (int p = 0; p < 32; p++) {
            int c = cb + (p << 1);
            float xv = x[(size_t)n * 262144 + (size_t)c * 4096 + ij0 + tl];
            sxa[tl * 76 + c] = __float2bfloat16((xv - mu) * rs * gw[c] + gb[c]);
        }
    }
    __syncthreads();
    int lane = tid & 31, wrp = tid >> 5;
    int g = lane >> 2, tt = lane & 3;
    int r0 = wrp * 16 + g, r1 = r0 + 8;
    unsigned a0[4], a1[4], a2[4], a3[4];
#pragma unroll
    for (int kk = 0; kk < 4; kk++) {
        int kbv = kk * 16;
        a0[kk] = *(const unsigned*)(sxa + r0 * 76 + kbv + tt * 2);
        a1[kk] = *(const unsigned*)(sxa + r1 * 76 + kbv + tt * 2);
        a2[kk] = *(const unsigned*)(sxa + r0 * 76 + kbv + 8 + tt * 2);
        a3[kk] = *(const unsigned*)(sxa + r1 * 76 + kbv + 8 + tt * 2);
    }
    size_t tok0 = (size_t)(t0 + r0) * 64, tok1 = (size_t)(t0 + r1) * 64;
#pragma unroll
    for (int jj = 0; jj < 24; jj++) {
        int nn = jj * 8 + g;
        float acc[4] = {0.f, 0.f, 0.f, 0.f};
#pragma unroll
        for (int kk = 0; kk < 4; kk++) {
            unsigned b0 = *(const unsigned*)(sw + nn * 72 + kk * 16 + tt * 2);
            unsigned b1 = *(const unsigned*)(sw + nn * 72 + kk * 16 + 8 + tt * 2);
            mma16816(acc, a0[kk], a1[kk], a2[kk], a3[kk], b0, b1);
        }
        int f0 = jj * 8 + tt * 2;
        float e00 = acc[0] + sb[f0], e01 = acc[1] + sb[f0 + 1];
        float e10 = acc[2] + sb[f0], e11 = acc[3] + sb[f0 + 1];
        if (f0 < 64) {
            *(__nv_bfloat162*)(g_qb + tok0 + f0) = __floats2bfloat162_rn(e00 * 0.25f, e01 * 0.25f);
            *(__nv_bfloat162*)(g_qb + tok1 + f0) = __floats2bfloat162_rn(e10 * 0.25f, e11 * 0.25f);
        } else if (f0 < 128) {
            *(__nv_bfloat162*)(g_kb + tok0 + f0 - 64) = __floats2bfloat162_rn(e00, e01);
            *(__nv_bfloat162*)(g_kb + tok1 + f0 - 64) = __floats2bfloat162_rn(e10, e11);
        } else {
            *(__nv_bfloat162*)(g_vb + tok0 + f0 - 128) = __floats2bfloat162_rn(e00, e01);
            *(__nv_bfloat162*)(g_vb + tok1 + f0 - 128) = __floats2bfloat162_rn(e10, e11);
        }
    }
}

// ---------------- K4: fused attention (query-paired) + out-proj + residual ----------------
// 128 thr: warp = head, thread = 2 adjacent queries sharing a 7x8 union window.
#define WMX 14
#define PB  72
__global__ __launch_bounds__(128, 4) void k_attn(const float* __restrict__ rpb,
                       const float* __restrict__ x, const float* __restrict__ pb) {
    extern __shared__ __align__(16) char smraw[];
    __nv_bfloat16* skb = (__nv_bfloat16*)smraw;           // 196*72
    __nv_bfloat16* svb = skb + 196 * PB;                  // 196*72
    float* sbp = (float*)(smraw + 56448);                 // 64
    // phase-2 aliases:
    __nv_bfloat16* sa = (__nv_bfloat16*)smraw;            // 64*72
    __nv_bfloat16* sw = (__nv_bfloat16*)(smraw + 9216);   // 64*72
    float* sxr = (float*)(smraw + 28224);                 // 64*66

    int tid = threadIdx.x, b = blockIdx.x;
    int n = b >> 6, t = b & 63;
    int i0 = (t >> 3) << 3, j0 = (t & 7) << 3;
    if (tid < 64) sbp[tid] = pb[tid];
    int rlo = max(i0 - 3, 0), rhi = min(i0 + 10, 63);
    int clo = max(j0 - 3, 0), chi = min(j0 + 10, 63);
    int nr = rhi - rlo + 1, nc = chi - clo + 1;
    int tot = nr * nc * 8;
    for (int idx = tid; idx < tot; idx += 128) {
        int c8 = idx & 7, p = idx >> 3;
        int lr = p / nc, lc = p - lr * nc;
        size_t gt = ((size_t)(n << 12) + ((rlo + lr) << 6) + (clo + lc)) * 64;
        uint4 kv = ((const uint4*)(g_kb + gt))[c8];
        uint4 vv = ((const uint4*)(g_vb + gt))[c8];
        int pp = lr * WMX + lc;
        ((uint4*)(skb + pp * PB))[c8] = kv;
        ((uint4*)(svb + pp * PB))[c8] = vv;
    }
    if (nc < WMX) {   // zero the first unwritten column (reachable at right-clip)
        for (int idx = tid; idx < 224; idx += 128) {
            int a = idx >> 7;             // 0=K, 1=V
            int p = (idx & 127) >> 3, c8 = idx & 7;
            if (p < WMX) {
                __nv_bfloat16* base = a ? svb : skb;
                ((uint4*)(base + (p * WMX + nc) * PB))[c8] = make_uint4(0, 0, 0, 0);
            }
        }
    }
    __syncthreads();

    int h = tid >> 5, pair = tid & 31;          // warp = one head, 32 query pairs
    int qi = pair >> 2, jp = (pair & 3) << 1;   // pair covers (qi, jp) and (qi, jp+1)
    int i = i0 + qi, jA = j0 + jp;
    int sh_ = min(max(i - 3, 0), 57);
    int swA = min(max(jA - 3, 0), 57), swB = min(max(jA - 2, 0), 57);
    int d1 = swB - swA;                          // 0 or 1
    int lsh = sh_ - rlo, lc0 = swA - clo;
    size_t tokA = (size_t)(n << 12) + (i << 6) + jA;
    const uint4* qpA = (const uint4*)(g_qb + tokA * 64 + h * 16);
    const uint4* qpB = (const uint4*)(g_qb + (tokA + 1) * 64 + h * 16);
    uint4 QA0 = qpA[0], QA1 = qpA[1], QB0 = qpB[0], QB1 = qpB[1];
    __nv_bfloat162 qA[8], qB[8];
    qA[0]=asbf2(QA0.x); qA[1]=asbf2(QA0.y); qA[2]=asbf2(QA0.z); qA[3]=asbf2(QA0.w);
    qA[4]=asbf2(QA1.x); qA[5]=asbf2(QA1.y); qA[6]=asbf2(QA1.z); qA[7]=asbf2(QA1.w);
    qB[0]=asbf2(QB0.x); qB[1]=asbf2(QB0.y); qB[2]=asbf2(QB0.z); qB[3]=asbf2(QB0.w);
    qB[4]=asbf2(QB1.x); qB[5]=asbf2(QB1.y); qB[6]=asbf2(QB1.z); qB[7]=asbf2(QB1.w);
    const __nv_bfloat16* kbase = skb + h * 16;
    const __nv_bfloat16* vbase = svb + h * 16;
    // bias base: rpb[h][i+6-pr][jA+6-pc]; pr = sh_+rr, pc = swA+cc
    const float* rbA = rpb + h * 169 + (i + 6 - sh_) * 13 + (jA + 6 - swA);
    const __nv_bfloat162 hz = __floats2bfloat162_rn(0.f, 0.f);
    ull vaccA[8] = {}, vaccB[8] = {};
    float ssumA = 0.f, ssumB = 0.f;
    for (int rr = 0; rr < 7; rr++) {
        int rowo = (lsh + rr) * WMX + lc0;
        const float* rb = rbA - rr * 13;
#pragma unroll
        for (int cc = 0; cc < 8; cc++) {
            int po = (rowo + cc) * PB;
            const uint4* kp = (const uint4*)(kbase + po);
            uint4 A = kp[0], B = kp[1];
            __nv_bfloat162 k0 = asbf2(A.x), k1 = asbf2(A.y), k2 = asbf2(A.z), k3 = asbf2(A.w);
            __nv_bfloat162 k4 = asbf2(B.x), k5 = asbf2(B.y), k6 = asbf2(B.z), k7 = asbf2(B.w);
            float eA = 0.f, eB = 0.f;
            if (cc < 7) {   // query A valid for cc 0..6
                __nv_bfloat162 a0 = __hfma2(qA[0], k0, hz), a1 = __hfma2(qA[1], k1, hz);
                a0 = __hfma2(qA[2], k2, a0); a1 = __hfma2(qA[3], k3, a1);
                a0 = __hfma2(qA[4], k4, a0); a1 = __hfma2(qA[5], k5, a1);
                a0 = __hfma2(qA[6], k6, a0); a1 = __hfma2(qA[7], k7, a1);
                __nv_bfloat162 hs = __hadd2(a0, a1);
                float sA = __bfloat162float(__low2bfloat16(hs))
                         + __bfloat162float(__high2bfloat16(hs)) + __ldg(rb - cc);
                eA = __expf(sA);
            }
            {   // query B
                __nv_bfloat162 b0 = __hfma2(qB[0], k0, hz), b1 = __hfma2(qB[1], k1, hz);
                b0 = __hfma2(qB[2], k2, b0); b1 = __hfma2(qB[3], k3, b1);
                b0 = __hfma2(qB[4], k4, b0); b1 = __hfma2(qB[5], k5, b1);
                b0 = __hfma2(qB[6], k6, b0); b1 = __hfma2(qB[7], k7, b1);
                __nv_bfloat162 hs = __hadd2(b0, b1);
                float sB = __bfloat162float(__low2bfloat16(hs))
                         + __bfloat162float(__high2bfloat16(hs)) + __ldg(rb + 1 - cc);
                eB = __expf(sB);
                if (cc == 0) eB = d1 ? 0.f : eB;      // B window starts at d1
                if (cc == 7) eB = d1 ? eB : 0.f;      // B reaches cc=7 only if d1
            }
            ssumA += eA; ssumB += eB;
            ull e2A = dup2(eA), e2B = dup2(eB);
            const uint4* vp = (const uint4*)(vbase + po);
            uint4 VA = vp[0], VB = vp[1];
            ull v0 = b2p(VA.x), v1 = b2p(VA.y), v2 = b2p(VA.z), v3 = b2p(VA.w);
            ull v4 = b2p(VB.x), v5 = b2p(VB.y), v6 = b2p(VB.z), v7 = b2p(VB.w);
            if (cc < 7) {
                fma2(vaccA[0], e2A, v0); fma2(vaccA[1], e2A, v1);
                fma2(vaccA[2], e2A, v2); fma2(vaccA[3], e2A, v3);
                fma2(vaccA[4], e2A, v4); fma2(vaccA[5], e2A, v5);
                fma2(vaccA[6], e2A, v6); fma2(vaccA[7], e2A, v7);
            }
            fma2(vaccB[0], e2B, v0); fma2(vaccB[1], e2B, v1);
            fma2(vaccB[2], e2B, v2); fma2(vaccB[3], e2B, v3);
            fma2(vaccB[4], e2B, v4); fma2(vaccB[5], e2B, v5);
            fma2(vaccB[6], e2B, v6); fma2(vaccB[7], e2B, v7);
        }
    }
    float invA = __fdividef(1.f, ssumA), invB = __fdividef(1.f, ssumB);
    unsigned obA[8], obB[8];
#pragma unroll
    for (int dd = 0; dd < 8; dd++) {
        float2 fa = up2(vaccA[dd]), fb = up2(vaccB[dd]);
        obA[dd] = asu(__floats2bfloat162_rn(fa.x * invA, fa.y * invA));
        obB[dd] = asu(__floats2bfloat162_rn(fb.x * invB, fb.y * invB));
    }
    __syncthreads();   // all K/V reads done; smem reusable

    // ---- phase 2: out-proj + residual ----
    int tA = qi * 8 + jp;
    *(uint4*)(sa + tA * 72 + h * 16)           = make_uint4(obA[0], obA[1], obA[2], obA[3]);
    *(uint4*)(sa + tA * 72 + h * 16 + 8)       = make_uint4(obA[4], obA[5], obA[6], obA[7]);
    *(uint4*)(sa + (tA + 1) * 72 + h * 16)     = make_uint4(obB[0], obB[1], obB[2], obB[3]);
    *(uint4*)(sa + (tA + 1) * 72 + h * 16 + 8) = make_uint4(obB[4], obB[5], obB[6], obB[7]);
    for (int idx = tid; idx < 512; idx += 128) {
        int r = idx >> 3, c8 = idx & 7;
        *(uint4*)(sw + r * 72 + c8 * 8) = *(const uint4*)(g_wpb + r * 64 + c8 * 8);
    }
    for (int idx = tid; idx < 4096; idx += 128) {
        int c = idx >> 6, lt = idx & 63;
        sxr[lt * 66 + c] =
            x[(size_t)n * 262144 + (size_t)c * 4096 + ((i0 + (lt >> 3)) << 6) + j0 + (lt & 7)];
    }
    __syncthreads();

    int lane = tid & 31, wrp = tid >> 5;         // 4 warps: warp = m16-tile, full n=64
    int g = lane >> 2, tt = lane & 3;
    int r0 = wrp * 16 + g, r1 = r0 + 8;
    unsigned a0[4], a1[4], a2[4], a3[4];
#pragma unroll
    for (int kk = 0; kk < 4; kk++) {
        int kbv = kk * 16;
        a0[kk] = *(const unsigned*)(sa + r0 * 72 + kbv + tt * 2);
        a1[kk] = *(const unsigned*)(sa + r1 * 72 + kbv + tt * 2);
        a2[kk] = *(const unsigned*)(sa + r0 * 72 + kbv + 8 + tt * 2);
        a3[kk] = *(const unsigned*)(sa + r1 * 72 + kbv + 8 + tt * 2);
    }
    size_t gt0 = (size_t)((n << 12) + ((i0 + (r0 >> 3)) << 6) + j0 + (r0 & 7)) * 64;
    size_t gt1 = (size_t)((n << 12) + ((i0 + (r1 >> 3)) << 6) + j0 + (r1 & 7)) * 64;
#pragma unroll
    for (int jj = 0; jj < 8; jj++) {
        int nn = jj * 8 + g;
        float acc[4] = {0.f, 0.f, 0.f, 0.f};
#pragma unroll
        for (int kk = 0; kk < 4; kk++) {
            unsigned b0 = *(const unsigned*)(sw + nn * 72 + kk * 16 + tt * 2);
            unsigned b1 = *(const unsigned*)(sw + nn * 72 + kk * 16 + 8 + tt * 2);
            mma16816(acc, a0[kk], a1[kk], a2[kk], a3[kk], b0, b1);
        }
        int c0 = jj * 8 + tt * 2;
        *(float2*)(g_y + gt0 + c0) = make_float2(
            acc[0] + sbp[c0] + sxr[r0 * 66 + c0],
            acc[1] + sbp[c0 + 1] + sxr[r0 * 66 + c0 + 1]);
        *(float2*)(g_y + gt1 + c0) = make_float2(
            acc[2] + sbp[c0] + sxr[r1 * 66 + c0],
            acc[3] + sbp[c0 + 1] + sxr[r1 * 66 + c0 + 1]);
    }
}

// ---------------- K6: LN + fc1 + GELU(tanh) + fc2 + residual + NCHW ----------------
__global__ __launch_bounds__(512, 2) void k_mlp(const float* __restrict__ lw, const float* __restrict__ lb,
                      const float* __restrict__ b1, const float* __restrict__ b2,
                      float* __restrict__ out) {
    extern __shared__ __align__(16) char smraw[];
    float* syn = (float*)smraw;
    __nv_bfloat16* sxa = (__nv_bfloat16*)(smraw + 8448);
    __nv_bfloat16* w1s = (__nv_bfloat16*)(smraw + 13056);
    __nv_bfloat16* w2s = (__nv_bfloat16*)(smraw + 49920);
    __nv_bfloat16* sh  = (__nv_bfloat16*)(smraw + 83712);
    float* sb1 = (float*)(smraw + 100608);
    float* sb2 = (float*)(smraw + 101632);
    int tid = threadIdx.x;
    for (int i = tid; i < 2048; i += 512) {
        int r = i >> 3, c8 = i & 7;
        *(uint4*)(w1s + r * 72 + c8 * 8) = *(const uint4*)(g_w1b + r * 64 + c8 * 8);
    }
    for (int i = tid; i < 2048; i += 512) {
        int r = i >> 5, c32 = i & 31;
        *(uint4*)(w2s + r * 264 + c32 * 8) = *(const uint4*)(g_w2b + r * 256 + c32 * 8);
    }
    if (tid < 256) sb1[tid] = b1[tid];
    if (tid < 64)  sb2[tid] = b2[tid];
    __syncthreads();

    int lane = tid & 31, wrp = tid >> 5;
    int g = lane >> 2, tt = lane & 3;
    int mi = wrp & 1, ngrp = wrp >> 1;
    int r0 = mi * 16 + g, r1 = r0 + 8;

    for (int it = 0; it < 4; it++) {
        int t0 = blockIdx.x * 128 + it * 32;
        int n = t0 >> 12, ij0 = t0 & 4095;
        for (int i = tid; i < 2048; i += 512)
            syn[(i >> 6) * 66 + (i & 63)] = g_y[(size_t)t0 * 64 + i];
        __syncthreads();
        {
            int tl = tid >> 4, qq = tid & 15;
            float s = 0.f, sq = 0.f;
#pragma unroll
            for (int cc = 0; cc < 4; cc++) {
                float v = syn[tl * 66 + qq * 4 + cc];
                s += v; sq += v * v;
            }
#pragma unroll
            for (int st = 1; st < 16; st <<= 1) {
                s  += __shfl_xor_sync(0xffffffffu, s, st);
                sq += __shfl_xor_sync(0xffffffffu, sq, st);
            }
            float mu = s * (1.f / 64.f);
            float rstd = rsqrtf(sq * (1.f / 64.f) - mu * mu + 1e-5f);
#pragma unroll
            for (int cc = 0; cc < 4; cc++) {
                int c = qq * 4 + cc;
                float v = syn[tl * 66 + c];
                sxa[tl * 72 + c] = __float2bfloat16((v - mu) * rstd * lw[c] + lb[c]);
            }
        }
        __syncthreads();
        {
            float acc[4][4];
#pragma unroll
            for (int jj = 0; jj < 4; jj++)
#pragma unroll
                for (int dd = 0; dd < 4; dd++) acc[jj][dd] = 0.f;
#pragma unroll
            for (int kk = 0; kk < 4; kk++) {
                int kbv = kk * 16;
                unsigned a0 = *(const unsigned*)(sxa + r0 * 72 + kbv + tt * 2);
                unsigned a1 = *(const unsigned*)(sxa + r1 * 72 + kbv + tt * 2);
                unsigned a2 = *(const unsigned*)(sxa + r0 * 72 + kbv + 8 + tt * 2);
                unsigned a3 = *(const unsigned*)(sxa + r1 * 72 + kbv + 8 + tt * 2);
#pragma unroll
                for (int jj = 0; jj < 4; jj++) {
                    int nn = ngrp * 32 + jj * 8 + g;
                    unsigned b0 = *(const unsigned*)(w1s + nn * 72 + kbv + tt * 2);
                    unsigned b1v = *(const unsigned*)(w1s + nn * 72 + kbv + 8 + tt * 2);
                    mma16816(acc[jj], a0, a1, a2, a3, b0, b1v);
                }
            }
#pragma unroll
            for (int jj = 0; jj < 4; jj++) {
                int c0 = ngrp * 32 + jj * 8 + tt * 2;
                float v00 = gelu_f(acc[jj][0] + sb1[c0]);
                float v01 = gelu_f(acc[jj][1] + sb1[c0 + 1]);
                float v10 = gelu_f(acc[jj][2] + sb1[c0]);
                float v11 = gelu_f(acc[jj][3] + sb1[c0 + 1]);
                *(__nv_bfloat162*)(sh + r0 * 264 + c0) = __floats2bfloat162_rn(v00, v01);
                *(__nv_bfloat162*)(sh + r1 * 264 + c0) = __floats2bfloat162_rn(v10, v11);
            }
        }
        __syncthreads();
        {
            float acc[4] = {0.f, 0.f, 0.f, 0.f};
            int nn = ngrp * 8 + g;
#pragma unroll 4
            for (int kk = 0; kk < 16; kk++) {
                int kbv = kk * 16;
                unsigned a0 = *(const unsigned*)(sh + r0 * 264 + kbv + tt * 2);
                unsigned a1 = *(const unsigned*)(sh + r1 * 264 + kbv + tt * 2);
                unsigned a2 = *(const unsigned*)(sh + r0 * 264 + kbv + 8 + tt * 2);
                unsigned a3 = *(const unsigned*)(sh + r1 * 264 + kbv + 8 + tt * 2);
                unsigned b0 = *(const unsigned*)(w2s + nn * 264 + kbv + tt * 2);
                unsigned b1v = *(const unsigned*)(w2s + nn * 264 + kbv + 8 + tt * 2);
                mma16816(acc, a0, a1, a2, a3, b0, b1v);
            }
            int c0 = ngrp * 8 + tt * 2;
            syn[r0 * 66 + c0]     = acc[0] + sb2[c0]     + syn[r0 * 66 + c0];
            syn[r0 * 66 + c0 + 1] = acc[1] + sb2[c0 + 1] + syn[r0 * 66 + c0 + 1];
            syn[r1 * 66 + c0]     = acc[2] + sb2[c0]     + syn[r1 * 66 + c0];
            syn[r1 * 66 + c0 + 1] = acc[3] + sb2[c0 + 1] + syn[r1 * 66 + c0 + 1];
        }
        __syncthreads();
        {
            int tl = tid & 31;
#pragma unroll
            for (int p = 0; p < 4; p++) {
                int c = (tid >> 5) + (p << 4);
                out[(size_t)n * 262144 + (size_t)c * 4096 + ij0 + tl] = syn[tl * 66 + c];
            }
        }
        __syncthreads();
    }
}

// ---------------- launch ----------------
extern "C" void kernel_launch(void* const* d_in, const int* in_sizes, int n_in,
                              void* d_out, int out_size) {
    const float* x      = (const float*)d_in[0];
    const float* gn_w   = (const float*)d_in[1];
    const float* gn_b   = (const float*)d_in[2];
    const float* qkv_w  = (const float*)d_in[3];
    const float* qkv_b  = (const float*)d_in[4];
    const float* rpb    = (const float*)d_in[5];
    const float* proj_w = (const float*)d_in[6];
    const float* proj_b = (const float*)d_in[7];
    const float* ln_w   = (const float*)d_in[8];
    const float* ln_b   = (const float*)d_in[9];
    const float* fc1_w  = (const float*)d_in[10];
    const float* fc1_b  = (const float*)d_in[11];
    const float* fc2_w  = (const float*)d_in[12];
    const float* fc2_b  = (const float*)d_in[13];
    float* out = (float*)d_out;

    size_t sm_qkv  = 47872;
    size_t sm_attn = 56704;    // -> 4 blocks/SM
    size_t sm_mlp  = 101888;   // -> 2 blocks/SM

    cudaFuncSetAttribute(k_qkv,  cudaFuncAttributeMaxDynamicSharedMemorySize, (int)sm_qkv);
    cudaFuncSetAttribute(k_attn, cudaFuncAttributeMaxDynamicSharedMemorySize, (int)sm_attn);
    cudaFuncSetAttribute(k_mlp,  cudaFuncAttributeMaxDynamicSharedMemorySize, (int)sm_mlp);

    k_prep  <<<96, 256>>>(fc1_w, fc2_w, qkv_w, proj_w);
    k_stats1<<<256, 256>>>(x);
    k_qkv <<<256, 256, sm_qkv>>>(x, gn_w, gn_b, qkv_b);
    k_attn<<<512, 128, sm_attn>>>(rpb, x, proj_b);
    k_mlp <<<256, 512, sm_mlp>>>(ln_w, ln_b, fc1_b, fc2_b, out);
}

// round 16
// speedup vs baseline: 1.1944x; 1.0004x over previous
#include <cuda_runtime.h>
#include <cuda_bf16.h>
#include <cuda_fp16.h>
#include <math.h>

#define NSAMP 8
#define NTOK  32768

typedef unsigned long long ull;

// ---------------- helpers ----------------
__device__ __forceinline__ __nv_bfloat162 asbf2(unsigned u) {
    return *reinterpret_cast<__nv_bfloat162*>(&u);
}
__device__ __forceinline__ __half2 ash2(unsigned u) {
    return *reinterpret_cast<__half2*>(&u);
}
__device__ __forceinline__ unsigned asu(__nv_bfloat162 v) {
    return *reinterpret_cast<unsigned*>(&v);
}
__device__ __forceinline__ float gelu_f(float v) {
    float u = 0.7978845608f * v * (1.f + 0.044715f * v * v);
    float t; asm("tanh.approx.f32 %0, %1;" : "=f"(t) : "f"(u));
    return 0.5f * v * (1.f + t);
}
__device__ __forceinline__ void ldsm4(unsigned& d0, unsigned& d1, unsigned& d2,
                                      unsigned& d3, unsigned addr) {
    asm volatile("ldmatrix.sync.aligned.m8n8.x4.shared.b16 {%0,%1,%2,%3}, [%4];"
        : "=r"(d0), "=r"(d1), "=r"(d2), "=r"(d3) : "r"(addr));
}
__device__ __forceinline__ void ldsm2(unsigned& d0, unsigned& d1, unsigned addr) {
    asm volatile("ldmatrix.sync.aligned.m8n8.x2.shared.b16 {%0,%1}, [%2];"
        : "=r"(d0), "=r"(d1) : "r"(addr));
}

// ---------------- mma.sync m16n8k16 bf16 ----------------
__device__ __forceinline__ void mma16816(float* d, unsigned a0, unsigned a1,
                                         unsigned a2, unsigned a3,
                                         unsigned b0, unsigned b1) {
    asm("mma.sync.aligned.m16n8k16.row.col.f32.bf16.bf16.f32 "
        "{%0,%1,%2,%3}, {%4,%5,%6,%7}, {%8,%9}, {%0,%1,%2,%3};"
        : "+f"(d[0]), "+f"(d[1]), "+f"(d[2]), "+f"(d[3])
        : "r"(a0), "r"(a1), "r"(a2), "r"(a3), "r"(b0), "r"(b1));
}

// ---------------- scratch ----------------
__device__ float g_part[256][2];
__device__ __nv_bfloat16 g_qb[NTOK * 64];
__device__ __nv_bfloat16 g_kb[NTOK * 64];
__device__ __half g_vh[NTOK * 64];
__device__ float g_y[NTOK * 64];
__device__ __nv_bfloat16 g_w1b[16384];
__device__ __nv_bfloat16 g_w2b[16384];
__device__ __nv_bfloat16 g_wqb[12288];
__device__ __nv_bfloat16 g_wpb[4096];

// ---------------- K0: weight pre-conversion ----------------
__global__ void k_prep(const float* __restrict__ w1, const float* __restrict__ w2,
                       const float* __restrict__ qw, const float* __restrict__ pw) {
    int i = blockIdx.x * 256 + threadIdx.x;
    const float* src; __nv_bfloat16* dst; int off;
    if (i < 8192)       { src = w1; dst = g_w1b; off = i; }
    else if (i < 16384) { src = w2; dst = g_w2b; off = i - 8192; }
    else if (i < 22528) { src = qw; dst = g_wqb; off = i - 16384; }
    else                { src = pw; dst = g_wpb; off = i - 22528; }
    float2 v = ((const float2*)src)[off];
    *(__nv_bfloat162*)(dst + off * 2) = __floats2bfloat162_rn(v.x, v.y);
}

// ---------------- K1: per-sample partial sum / sumsq ----------------
__global__ void k_stats1(const float* __restrict__ x) {
    __shared__ float rs_[256], rq_[256];
    int b = blockIdx.x;
    int n = b >> 5, ch = b & 31;
    const float4* p = (const float4*)(x + (size_t)n * 262144 + (size_t)ch * 8192);
    float s = 0.f, sq = 0.f;
#pragma unroll
    for (int i = 0; i < 8; i++) {
        float4 v = p[threadIdx.x + i * 256];
        s  += v.x + v.y + v.z + v.w;
        sq += v.x * v.x + v.y * v.y + v.z * v.z + v.w * v.w;
    }
    rs_[threadIdx.x] = s; rq_[threadIdx.x] = sq;
    __syncthreads();
    for (int st = 128; st > 0; st >>= 1) {
        if (threadIdx.x < st) {
            rs_[threadIdx.x] += rs_[threadIdx.x + st];
            rq_[threadIdx.x] += rq_[threadIdx.x + st];
        }
        __syncthreads();
    }
    if (threadIdx.x == 0) { g_part[b][0] = rs_[0]; g_part[b][1] = rq_[0]; }
}

// ---------------- K3: stats-finalize + norm + QKV via bf16 mma ----------------
__global__ __launch_bounds__(256) void k_qkv(const float* __restrict__ x,
                      const float* __restrict__ gw, const float* __restrict__ gb,
                      const float* __restrict__ qkvb) {
    extern __shared__ __align__(16) char smraw[];
    __nv_bfloat16* sxa = (__nv_bfloat16*)smraw;           // 128*76
    __nv_bfloat16* sw  = (__nv_bfloat16*)(smraw + 19456); // 192*72
    float* sb = (float*)(smraw + 47104);                  // 192
    __shared__ float s_mu, s_rs;
    int tid = threadIdx.x;
    int t0 = blockIdx.x * 128;
    int n = t0 >> 12, ij0 = t0 & 4095;
    for (int i = tid; i < 1536; i += 256) {
        int r = i >> 3, c8 = i & 7;
        *(uint4*)(sw + r * 72 + c8 * 8) = *(const uint4*)(g_wqb + r * 64 + c8 * 8);
    }
    if (tid < 192) sb[tid] = qkvb[tid];
    if (tid < 32) {
        float s  = g_part[n * 32 + tid][0];
        float sq = g_part[n * 32 + tid][1];
#pragma unroll
        for (int st = 16; st > 0; st >>= 1) {
            s  += __shfl_xor_sync(0xffffffffu, s, st);
            sq += __shfl_xor_sync(0xffffffffu, sq, st);
        }
        if (tid == 0) {
            float mu  = s * (1.f / 262144.f);
            float var = sq * (1.f / 262144.f) - mu * mu;
            s_mu = mu;
            s_rs = rsqrtf(var + 1e-5f);
        }
    }
    __syncthreads();
    float mu = s_mu, rs = s_rs;
    {
        int tl = tid & 127, cb = tid >> 7;
#pragma unroll
        for (int p = 0; p < 32; p++) {
            int c = cb + (p << 1);
            float xv = x[(size_t)n * 262144 + (size_t)c * 4096 + ij0 + tl];
            sxa[tl * 76 + c] = __float2bfloat16((xv - mu) * rs * gw[c] + gb[c]);
        }
    }
    __syncthreads();
    int lane = tid & 31, wrp = tid >> 5;
    int g = lane >> 2, tt = lane & 3;
    int r0 = wrp * 16 + g, r1 = r0 + 8;
    unsigned a0[4], a1[4], a2[4], a3[4];
#pragma unroll
    for (int kk = 0; kk < 4; kk++) {
        int kbv = kk * 16;
        a0[kk] = *(const unsigned*)(sxa + r0 * 76 + kbv + tt * 2);
        a1[kk] = *(const unsigned*)(sxa + r1 * 76 + kbv + tt * 2);
        a2[kk] = *(const unsigned*)(sxa + r0 * 76 + kbv + 8 + tt * 2);
        a3[kk] = *(const unsigned*)(sxa + r1 * 76 + kbv + 8 + tt * 2);
    }
    size_t tok0 = (size_t)(t0 + r0) * 64, tok1 = (size_t)(t0 + r1) * 64;
#pragma unroll
    for (int jj = 0; jj < 24; jj++) {
        int nn = jj * 8 + g;
        float acc[4] = {0.f, 0.f, 0.f, 0.f};
#pragma unroll
        for (int kk = 0; kk < 4; kk++) {
            unsigned b0 = *(const unsigned*)(sw + nn * 72 + kk * 16 + tt * 2);
            unsigned b1 = *(const unsigned*)(sw + nn * 72 + kk * 16 + 8 + tt * 2);
            mma16816(acc, a0[kk], a1[kk], a2[kk], a3[kk], b0, b1);
        }
        int f0 = jj * 8 + tt * 2;
        float e00 = acc[0] + sb[f0], e01 = acc[1] + sb[f0 + 1];
        float e10 = acc[2] + sb[f0], e11 = acc[3] + sb[f0 + 1];
        if (f0 < 64) {
            *(__nv_bfloat162*)(g_qb + tok0 + f0) = __floats2bfloat162_rn(e00 * 0.25f, e01 * 0.25f);
            *(__nv_bfloat162*)(g_qb + tok1 + f0) = __floats2bfloat162_rn(e10 * 0.25f, e11 * 0.25f);
        } else if (f0 < 128) {
            *(__nv_bfloat162*)(g_kb + tok0 + f0 - 64) = __floats2bfloat162_rn(e00, e01);
            *(__nv_bfloat162*)(g_kb + tok1 + f0 - 64) = __floats2bfloat162_rn(e10, e11);
        } else {
            *(__half2*)(g_vh + tok0 + f0 - 128) = __floats2half2_rn(e00, e01);
            *(__half2*)(g_vh + tok1 + f0 - 128) = __floats2half2_rn(e10, e11);
        }
    }
}

// ---------------- K4: fused attention (query-paired, half V) + out-proj ----------------
#define WMX 14
#define PB  72
__global__ __launch_bounds__(128, 4) void k_attn(const float* __restrict__ rpb,
                       const float* __restrict__ x, const float* __restrict__ pb) {
    extern __shared__ __align__(16) char smraw[];
    __nv_bfloat16* skb = (__nv_bfloat16*)smraw;           // 196*72 bf16 K
    __half*        svh = (__half*)(smraw + 28224);        // 196*72 half V
    float* sbp = (float*)(smraw + 56448);                 // 64
    // phase-2 aliases:
    __nv_bfloat16* sa = (__nv_bfloat16*)smraw;            // 64*72
    __nv_bfloat16* sw = (__nv_bfloat16*)(smraw + 9216);   // 64*72
    float* sxr = (float*)(smraw + 28224);                 // 64*66

    int tid = threadIdx.x, b = blockIdx.x;
    int n = b >> 6, t = b & 63;
    int i0 = (t >> 3) << 3, j0 = (t & 7) << 3;
    if (tid < 64) sbp[tid] = pb[tid];
    int rlo = max(i0 - 3, 0), rhi = min(i0 + 10, 63);
    int clo = max(j0 - 3, 0), chi = min(j0 + 10, 63);
    int nr = rhi - rlo + 1, nc = chi - clo + 1;
    int tot = nr * nc * 8;
    for (int idx = tid; idx < tot; idx += 128) {
        int c8 = idx & 7, p = idx >> 3;
        int lr = p / nc, lc = p - lr * nc;
        size_t gt = ((size_t)(n << 12) + ((rlo + lr) << 6) + (clo + lc)) * 64;
        uint4 kv = ((const uint4*)(g_kb + gt))[c8];
        uint4 vv = ((const uint4*)(g_vh + gt))[c8];
        int pp = lr * WMX + lc;
        ((uint4*)(skb + pp * PB))[c8] = kv;
        ((uint4*)(svh + pp * PB))[c8] = vv;
    }
    if (nc < WMX) {
        for (int idx = tid; idx < 224; idx += 128) {
            int a = idx >> 7;
            int p = (idx & 127) >> 3, c8 = idx & 7;
            if (p < WMX) {
                if (a) ((uint4*)(svh + (p * WMX + nc) * PB))[c8] = make_uint4(0, 0, 0, 0);
                else   ((uint4*)(skb + (p * WMX + nc) * PB))[c8] = make_uint4(0, 0, 0, 0);
            }
        }
    }
    __syncthreads();

    int h = tid >> 5, pair = tid & 31;
    int qi = pair >> 2, jp = (pair & 3) << 1;
    int i = i0 + qi, jA = j0 + jp;
    int sh_ = min(max(i - 3, 0), 57);
    int swA = min(max(jA - 3, 0), 57), swB = min(max(jA - 2, 0), 57);
    int d1 = swB - swA;
    int lsh = sh_ - rlo, lc0 = swA - clo;
    size_t tokA = (size_t)(n << 12) + (i << 6) + jA;
    const uint4* qpA = (const uint4*)(g_qb + tokA * 64 + h * 16);
    const uint4* qpB = (const uint4*)(g_qb + (tokA + 1) * 64 + h * 16);
    uint4 QA0 = qpA[0], QA1 = qpA[1], QB0 = qpB[0], QB1 = qpB[1];
    __nv_bfloat162 qA[8], qB[8];
    qA[0]=asbf2(QA0.x); qA[1]=asbf2(QA0.y); qA[2]=asbf2(QA0.z); qA[3]=asbf2(QA0.w);
    qA[4]=asbf2(QA1.x); qA[5]=asbf2(QA1.y); qA[6]=asbf2(QA1.z); qA[7]=asbf2(QA1.w);
    qB[0]=asbf2(QB0.x); qB[1]=asbf2(QB0.y); qB[2]=asbf2(QB0.z); qB[3]=asbf2(QB0.w);
    qB[4]=asbf2(QB1.x); qB[5]=asbf2(QB1.y); qB[6]=asbf2(QB1.z); qB[7]=asbf2(QB1.w);
    const __nv_bfloat16* kbase = skb + h * 16;
    const __half* vbase = svh + h * 16;
    const float* rbA = rpb + h * 169 + (i + 6 - sh_) * 13 + (jA + 6 - swA);
    const __nv_bfloat162 hz = __floats2bfloat162_rn(0.f, 0.f);
    __half2 vaccA[8], vaccB[8];
    const __half2 h2z = __floats2half2_rn(0.f, 0.f);
#pragma unroll
    for (int dd = 0; dd < 8; dd++) { vaccA[dd] = h2z; vaccB[dd] = h2z; }
    float ssumA = 0.f, ssumB = 0.f;
    for (int rr = 0; rr < 7; rr++) {
        int rowo = (lsh + rr) * WMX + lc0;
        const float* rb = rbA - rr * 13;
#pragma unroll
        for (int cc = 0; cc < 8; cc++) {
            int po = (rowo + cc) * PB;
            const uint4* kp = (const uint4*)(kbase + po);
            uint4 A = kp[0], B = kp[1];
            __nv_bfloat162 k0 = asbf2(A.x), k1 = asbf2(A.y), k2 = asbf2(A.z), k3 = asbf2(A.w);
            __nv_bfloat162 k4 = asbf2(B.x), k5 = asbf2(B.y), k6 = asbf2(B.z), k7 = asbf2(B.w);
            float eA = 0.f, eB = 0.f;
            if (cc < 7) {
                __nv_bfloat162 a0 = __hfma2(qA[0], k0, hz), a1 = __hfma2(qA[1], k1, hz);
                a0 = __hfma2(qA[2], k2, a0); a1 = __hfma2(qA[3], k3, a1);
                a0 = __hfma2(qA[4], k4, a0); a1 = __hfma2(qA[5], k5, a1);
                a0 = __hfma2(qA[6], k6, a0); a1 = __hfma2(qA[7], k7, a1);
                __nv_bfloat162 hs = __hadd2(a0, a1);
                float sA = __bfloat162float(__low2bfloat16(hs))
                         + __bfloat162float(__high2bfloat16(hs)) + __ldg(rb - cc);
                eA = __expf(sA);
            }
            {
                __nv_bfloat162 b0 = __hfma2(qB[0], k0, hz), b1 = __hfma2(qB[1], k1, hz);
                b0 = __hfma2(qB[2], k2, b0); b1 = __hfma2(qB[3], k3, b1);
                b0 = __hfma2(qB[4], k4, b0); b1 = __hfma2(qB[5], k5, b1);
                b0 = __hfma2(qB[6], k6, b0); b1 = __hfma2(qB[7], k7, b1);
                __nv_bfloat162 hs = __hadd2(b0, b1);
                float sB = __bfloat162float(__low2bfloat16(hs))
                         + __bfloat162float(__high2bfloat16(hs)) + __ldg(rb + 1 - cc);
                eB = __expf(sB);
                if (cc == 0) eB = d1 ? 0.f : eB;
                if (cc == 7) eB = d1 ? eB : 0.f;
            }
            ssumA += eA; ssumB += eB;
            __half2 e2A = __float2half2_rn(eA), e2B = __float2half2_rn(eB);
            const uint4* vp = (const uint4*)(vbase + po);
            uint4 VA = vp[0], VB = vp[1];
            __half2 v0 = ash2(VA.x), v1 = ash2(VA.y), v2 = ash2(VA.z), v3 = ash2(VA.w);
            __half2 v4 = ash2(VB.x), v5 = ash2(VB.y), v6 = ash2(VB.z), v7 = ash2(VB.w);
            if (cc < 7) {
                vaccA[0] = __hfma2(e2A, v0, vaccA[0]); vaccA[1] = __hfma2(e2A, v1, vaccA[1]);
                vaccA[2] = __hfma2(e2A, v2, vaccA[2]); vaccA[3] = __hfma2(e2A, v3, vaccA[3]);
                vaccA[4] = __hfma2(e2A, v4, vaccA[4]); vaccA[5] = __hfma2(e2A, v5, vaccA[5]);
                vaccA[6] = __hfma2(e2A, v6, vaccA[6]); vaccA[7] = __hfma2(e2A, v7, vaccA[7]);
            }
            vaccB[0] = __hfma2(e2B, v0, vaccB[0]); vaccB[1] = __hfma2(e2B, v1, vaccB[1]);
            vaccB[2] = __hfma2(e2B, v2, vaccB[2]); vaccB[3] = __hfma2(e2B, v3, vaccB[3]);
            vaccB[4] = __hfma2(e2B, v4, vaccB[4]); vaccB[5] = __hfma2(e2B, v5, vaccB[5]);
            vaccB[6] = __hfma2(e2B, v6, vaccB[6]); vaccB[7] = __hfma2(e2B, v7, vaccB[7]);
        }
    }
    float invA = __fdividef(1.f, ssumA), invB = __fdividef(1.f, ssumB);
    unsigned obA[8], obB[8];
#pragma unroll
    for (int dd = 0; dd < 8; dd++) {
        float2 fa = __half22float2(vaccA[dd]), fb = __half22float2(vaccB[dd]);
        obA[dd] = asu(__floats2bfloat162_rn(fa.x * invA, fa.y * invA));
        obB[dd] = asu(__floats2bfloat162_rn(fb.x * invB, fb.y * invB));
    }
    __syncthreads();

    // ---- phase 2: out-proj + residual ----
    int tA = qi * 8 + jp;
    *(uint4*)(sa + tA * 72 + h * 16)           = make_uint4(obA[0], obA[1], obA[2], obA[3]);
    *(uint4*)(sa + tA * 72 + h * 16 + 8)       = make_uint4(obA[4], obA[5], obA[6], obA[7]);
    *(uint4*)(sa + (tA + 1) * 72 + h * 16)     = make_uint4(obB[0], obB[1], obB[2], obB[3]);
    *(uint4*)(sa + (tA + 1) * 72 + h * 16 + 8) = make_uint4(obB[4], obB[5], obB[6], obB[7]);
    for (int idx = tid; idx < 512; idx += 128) {
        int r = idx >> 3, c8 = idx & 7;
        *(uint4*)(sw + r * 72 + c8 * 8) = *(const uint4*)(g_wpb + r * 64 + c8 * 8);
    }
    for (int idx = tid; idx < 4096; idx += 128) {
        int c = idx >> 6, lt = idx & 63;
        sxr[lt * 66 + c] =
            x[(size_t)n * 262144 + (size_t)c * 4096 + ((i0 + (lt >> 3)) << 6) + j0 + (lt & 7)];
    }
    __syncthreads();

    int lane = tid & 31, wrp = tid >> 5;
    int g = lane >> 2, tt = lane & 3;
    int r0 = wrp * 16 + g, r1 = r0 + 8;
    unsigned a0[4], a1[4], a2[4], a3[4];
#pragma unroll
    for (int kk = 0; kk < 4; kk++) {
        int kbv = kk * 16;
        a0[kk] = *(const unsigned*)(sa + r0 * 72 + kbv + tt * 2);
        a1[kk] = *(const unsigned*)(sa + r1 * 72 + kbv + tt * 2);
        a2[kk] = *(const unsigned*)(sa + r0 * 72 + kbv + 8 + tt * 2);
        a3[kk] = *(const unsigned*)(sa + r1 * 72 + kbv + 8 + tt * 2);
    }
    size_t gt0 = (size_t)((n << 12) + ((i0 + (r0 >> 3)) << 6) + j0 + (r0 & 7)) * 64;
    size_t gt1 = (size_t)((n << 12) + ((i0 + (r1 >> 3)) << 6) + j0 + (r1 & 7)) * 64;
#pragma unroll
    for (int jj = 0; jj < 8; jj++) {
        int nn = jj * 8 + g;
        float acc[4] = {0.f, 0.f, 0.f, 0.f};
#pragma unroll
        for (int kk = 0; kk < 4; kk++) {
            unsigned b0 = *(const unsigned*)(sw + nn * 72 + kk * 16 + tt * 2);
            unsigned b1 = *(const unsigned*)(sw + nn * 72 + kk * 16 + 8 + tt * 2);
            mma16816(acc, a0[kk], a1[kk], a2[kk], a3[kk], b0, b1);
        }
        int c0 = jj * 8 + tt * 2;
        *(float2*)(g_y + gt0 + c0) = make_float2(
            acc[0] + sbp[c0] + sxr[r0 * 66 + c0],
            acc[1] + sbp[c0 + 1] + sxr[r0 * 66 + c0 + 1]);
        *(float2*)(g_y + gt1 + c0) = make_float2(
            acc[2] + sbp[c0] + sxr[r1 * 66 + c0],
            acc[3] + sbp[c0 + 1] + sxr[r1 * 66 + c0 + 1]);
    }
}

// ---------------- K6: LN + fc1 + GELU + fc2 + residual + NCHW (ldmatrix) ----------------
__global__ __launch_bounds__(512, 2) void k_mlp(const float* __restrict__ lw, const float* __restrict__ lb,
                      const float* __restrict__ b1, const float* __restrict__ b2,
                      float* __restrict__ out) {
    extern __shared__ __align__(16) char smraw[];
    float* syn = (float*)smraw;                           // 32*66 f32
    __nv_bfloat16* sxa = (__nv_bfloat16*)(smraw + 8448);  // 32*72
    __nv_bfloat16* w1s = (__nv_bfloat16*)(smraw + 13056); // 256*72
    __nv_bfloat16* w2s = (__nv_bfloat16*)(smraw + 49920); // 64*264
    __nv_bfloat16* sh  = (__nv_bfloat16*)(smraw + 83712); // 32*264
    float* sb1 = (float*)(smraw + 100608);
    float* sb2 = (float*)(smraw + 101632);
    int tid = threadIdx.x;
    for (int i = tid; i < 2048; i += 512) {
        int r = i >> 3, c8 = i & 7;
        *(uint4*)(w1s + r * 72 + c8 * 8) = *(const uint4*)(g_w1b + r * 64 + c8 * 8);
    }
    for (int i = tid; i < 2048; i += 512) {
        int r = i >> 5, c32 = i & 31;
        *(uint4*)(w2s + r * 264 + c32 * 8) = *(const uint4*)(g_w2b + r * 256 + c32 * 8);
    }
    if (tid < 256) sb1[tid] = b1[tid];
    if (tid < 64)  sb2[tid] = b2[tid];
    __syncthreads();

    int lane = tid & 31, wrp = tid >> 5;
    int g = lane >> 2, tt = lane & 3;
    int mi = wrp & 1, ngrp = wrp >> 1;
    int r0 = mi * 16 + g, r1 = r0 + 8;
    // ldmatrix lane geometry: row = (l&7) + ((l>>3)&1)*8, col-half = (l>>4)*8
    int lr = (lane & 7) + ((lane >> 3) & 1) * 8;
    int lco = (lane >> 4) * 8;
    unsigned aA1 = (unsigned)__cvta_generic_to_shared(sxa + (mi * 16 + lr) * 72 + lco);
    unsigned bB1_0 = (unsigned)__cvta_generic_to_shared(w1s + (ngrp * 32 + lr) * 72 + lco);
    unsigned bB1_1 = (unsigned)__cvta_generic_to_shared(w1s + (ngrp * 32 + 16 + lr) * 72 + lco);
    unsigned aA2 = (unsigned)__cvta_generic_to_shared(sh + (mi * 16 + lr) * 264 + lco);
    unsigned bB2 = (unsigned)__cvta_generic_to_shared(
        w2s + (ngrp * 8 + (lane & 7)) * 264 + ((lane >> 3) & 1) * 8);

    for (int it = 0; it < 4; it++) {
        int t0 = blockIdx.x * 128 + it * 32;
        int n = t0 >> 12, ij0 = t0 & 4095;
        for (int i = tid; i < 2048; i += 512)
            syn[(i >> 6) * 66 + (i & 63)] = g_y[(size_t)t0 * 64 + i];
        __syncthreads();
        {   // LayerNorm -> sxa bf16
            int tl = tid >> 4, qq = tid & 15;
            float s = 0.f, sq = 0.f;
#pragma unroll
            for (int cc = 0; cc < 4; cc++) {
                float v = syn[tl * 66 + qq * 4 + cc];
                s += v; sq += v * v;
            }
#pragma unroll
            for (int st = 1; st < 16; st <<= 1) {
                s  += __shfl_xor_sync(0xffffffffu, s, st);
                sq += __shfl_xor_sync(0xffffffffu, sq, st);
            }
            float mu = s * (1.f / 64.f);
            float rstd = rsqrtf(sq * (1.f / 64.f) - mu * mu + 1e-5f);
#pragma unroll
            for (int cc = 0; cc < 4; cc++) {
                int c = qq * 4 + cc;
                float v = syn[tl * 66 + c];
                sxa[tl * 72 + c] = __float2bfloat16((v - mu) * rstd * lw[c] + lb[c]);
            }
        }
        __syncthreads();
        {   // fc1 via ldmatrix: m16 x n32 per warp
            float acc[4][4];
#pragma unroll
            for (int jj = 0; jj < 4; jj++)
#pragma unroll
                for (int dd = 0; dd < 4; dd++) acc[jj][dd] = 0.f;
#pragma unroll
            for (int kk = 0; kk < 4; kk++) {
                unsigned a0, a1, a2, a3;
                ldsm4(a0, a1, a2, a3, aA1 + kk * 32);
                unsigned b00, b01, b10, b11;
                ldsm4(b00, b01, b10, b11, bB1_0 + kk * 32);
                mma16816(acc[0], a0, a1, a2, a3, b00, b10);
                mma16816(acc[1], a0, a1, a2, a3, b01, b11);
                ldsm4(b00, b01, b10, b11, bB1_1 + kk * 32);
                mma16816(acc[2], a0, a1, a2, a3, b00, b10);
                mma16816(acc[3], a0, a1, a2, a3, b01, b11);
            }
#pragma unroll
            for (int jj = 0; jj < 4; jj++) {
                int c0 = ngrp * 32 + jj * 8 + tt * 2;
                float v00 = gelu_f(acc[jj][0] + sb1[c0]);
                float v01 = gelu_f(acc[jj][1] + sb1[c0 + 1]);
                float v10 = gelu_f(acc[jj][2] + sb1[c0]);
                float v11 = gelu_f(acc[jj][3] + sb1[c0 + 1]);
                *(__nv_bfloat162*)(sh + r0 * 264 + c0) = __floats2bfloat162_rn(v00, v01);
                *(__nv_bfloat162*)(sh + r1 * 264 + c0) = __floats2bfloat162_rn(v10, v11);
            }
        }
        __syncthreads();
        {   // fc2 via ldmatrix: m16 x n8 per warp
            float acc[4] = {0.f, 0.f, 0.f, 0.f};
#pragma unroll 4
            for (int kk = 0; kk < 16; kk++) {
                unsigned a0, a1, a2, a3;
                ldsm4(a0, a1, a2, a3, aA2 + kk * 32);
                unsigned b0, b1v;
                ldsm2(b0, b1v, bB2 + kk * 32);
                mma16816(acc, a0, a1, a2, a3, b0, b1v);
            }
            int c0 = ngrp * 8 + tt * 2;
            syn[r0 * 66 + c0]     = acc[0] + sb2[c0]     + syn[r0 * 66 + c0];
            syn[r0 * 66 + c0 + 1] = acc[1] + sb2[c0 + 1] + syn[r0 * 66 + c0 + 1];
            syn[r1 * 66 + c0]     = acc[2] + sb2[c0]     + syn[r1 * 66 + c0];
            syn[r1 * 66 + c0 + 1] = acc[3] + sb2[c0 + 1] + syn[r1 * 66 + c0 + 1];
        }
        __syncthreads();
        {   // coalesced NCHW write
            int tl = tid & 31;
#pragma unroll
            for (int p = 0; p < 4; p++) {
                int c = (tid >> 5) + (p << 4);
                out[(size_t)n * 262144 + (size_t)c * 4096 + ij0 + tl] = syn[tl * 66 + c];
            }
        }
        __syncthreads();
    }
}

// ---------------- launch ----------------
extern "C" void kernel_launch(void* const* d_in, const int* in_sizes, int n_in,
                              void* d_out, int out_size) {
    const float* x      = (const float*)d_in[0];
    const float* gn_w   = (const float*)d_in[1];
    const float* gn_b   = (const float*)d_in[2];
    const float* qkv_w  = (const float*)d_in[3];
    const float* qkv_b  = (const float*)d_in[4];
    const float* rpb    = (const float*)d_in[5];
    const float* proj_w = (const float*)d_in[6];
    const float* proj_b = (const float*)d_in[7];
    const float* ln_w   = (const float*)d_in[8];
    const float* ln_b   = (const float*)d_in[9];
    const float* fc1_w  = (const float*)d_in[10];
    const float* fc1_b  = (const float*)d_in[11];
    const float* fc2_w  = (const float*)d_in[12];
    const float* fc2_b  = (const float*)d_in[13];
    float* out = (float*)d_out;

    size_t sm_qkv  = 47872;
    size_t sm_attn = 56704;    // -> 4 blocks/SM
    size_t sm_mlp  = 101888;   // -> 2 blocks/SM

    cudaFuncSetAttribute(k_qkv,  cudaFuncAttributeMaxDynamicSharedMemorySize, (int)sm_qkv);
    cudaFuncSetAttribute(k_attn, cudaFuncAttributeMaxDynamicSharedMemorySize, (int)sm_attn);
    cudaFuncSetAttribute(k_mlp,  cudaFuncAttributeMaxDynamicSharedMemorySize, (int)sm_mlp);

    k_prep  <<<96, 256>>>(fc1_w, fc2_w, qkv_w, proj_w);
    k_stats1<<<256, 256>>>(x);
    k_qkv <<<256, 256, sm_qkv>>>(x, gn_w, gn_b, qkv_b);
    k_attn<<<512, 128, sm_attn>>>(rpb, x, proj_b);
    k_mlp <<<256, 512, sm_mlp>>>(ln_w, ln_b, fc1_b, fc2_b, out);
}